// round 6
// baseline (speedup 1.0000x reference)
#include <cuda_runtime.h>
#include <cuda_bf16.h>
#include <math.h>

#define LO 3072
#define LC 1024
#define LT 4096   // LO + LC
#define DM 1024   // model dim
#define NH 16
#define DH 64
#define MH 4096

// ---------------- scratch (device globals; no allocation allowed) ----------------
__device__ float g_mod[12 * DM];                 // [2 streams][6 chunks][1024]
__device__ float g_qkv[LT * 3 * DM];             // raw qkv fp32
__device__ __nv_bfloat16 g_xm[LT * DM];          // modulated LN output (bf16)
__device__ __nv_bfloat16 g_q[NH * LT * DH];      // [h][l][dh] (q pre-scaled by 0.125)
__device__ __nv_bfloat16 g_k[NH * LT * DH];
__device__ __nv_bfloat16 g_v[NH * LT * DH];
__device__ __nv_bfloat16 g_attn[LT * DM];        // attention out bf16
__device__ __nv_bfloat16 g_h[LT * MH];           // mlp hidden bf16
__device__ unsigned g_wb[12582912];              // pair-packed bf16 weights

// word offsets into g_wb
#define W_OQKV  0
#define W_CQKV  1572864
#define W_OPROJ 3145728
#define W_CPROJ 3670016
#define W_OMLP1 4194304
#define W_CMLP1 6291456
#define W_OMLP2 8388608
#define W_CMLP2 10485760

// ---------------- helpers ----------------
__device__ __forceinline__ void mma_bf16(float d[4], const unsigned a[4], const unsigned b[2]) {
    asm volatile(
        "mma.sync.aligned.m16n8k16.row.col.f32.bf16.bf16.f32 "
        "{%0,%1,%2,%3}, {%4,%5,%6,%7}, {%8,%9}, {%0,%1,%2,%3};"
        : "+f"(d[0]), "+f"(d[1]), "+f"(d[2]), "+f"(d[3])
        : "r"(a[0]), "r"(a[1]), "r"(a[2]), "r"(a[3]), "r"(b[0]), "r"(b[1]));
}

__device__ __forceinline__ unsigned pack_bf16(float lo, float hi) {
    unsigned short l = __bfloat16_as_ushort(__float2bfloat16_rn(lo));
    unsigned short h = __bfloat16_as_ushort(__float2bfloat16_rn(hi));
    return (unsigned)l | ((unsigned)h << 16);
}

__device__ __forceinline__ void cp_async16(unsigned saddr, const void* g) {
    asm volatile("cp.async.cg.shared.global [%0], [%1], 16;" :: "r"(saddr), "l"(g));
}

// ---------------- weight packer: [K][N] fp32 -> [K/2][N] u32 (bf16 pair along K) ----------------
__global__ void cvt_w_kernel(const float* __restrict__ w, unsigned* __restrict__ o,
                             int K2, int N) {
    int idx = blockIdx.x * 256 + threadIdx.x;
    if (idx >= K2 * N) return;
    int r = idx / N, n = idx - r * N;
    float lo = w[(size_t)(2 * r) * N + n];
    float hi = w[(size_t)(2 * r + 1) * N + n];
    o[idx] = pack_bf16(lo, hi);
}

// ---------------- modulation: silu(vec) @ mod_w + mod_b ----------------
__global__ void mod_kernel(const float* __restrict__ vec,
                           const float* __restrict__ ow, const float* __restrict__ ob,
                           const float* __restrict__ cw, const float* __restrict__ cb) {
    __shared__ float sv[DM];
    int tid = threadIdx.x;
    for (int i = tid; i < DM; i += 256) {
        float v = vec[i];
        sv[i] = v / (1.0f + expf(-v));
    }
    __syncthreads();
    int j = blockIdx.x * 256 + tid;          // 0 .. 12287
    int stream = j / (6 * DM);
    int jj = j % (6 * DM);
    const float* w = stream ? cw : ow;
    const float* b = stream ? cb : ob;
    float acc = 0.0f;
    for (int i = 0; i < DM; i++)
        acc += sv[i] * w[(size_t)i * (6 * DM) + jj];
    g_mod[stream * 6 * DM + jj] = acc + b[jj];
}

// ---------------- layernorm + modulation -> bf16 ----------------
__global__ void ln_mod_kernel(const float* __restrict__ x, __nv_bfloat16* __restrict__ y,
                              int stream, int shiftc, int scalec) {
    int row = blockIdx.x;
    int tid = threadIdx.x;
    const float* xr = x + (size_t)row * DM;
    __shared__ float r1[256], r2[256];
    float s = 0.0f, ss = 0.0f;
    for (int c = tid; c < DM; c += 256) {
        float v = xr[c];
        s += v; ss += v * v;
    }
    r1[tid] = s; r2[tid] = ss;
    __syncthreads();
    for (int st = 128; st > 0; st >>= 1) {
        if (tid < st) { r1[tid] += r1[tid + st]; r2[tid] += r2[tid + st]; }
        __syncthreads();
    }
    float mean = r1[0] * (1.0f / DM);
    float var = r2[0] * (1.0f / DM) - mean * mean;
    float inv = rsqrtf(var + 1e-6f);
    const float* sh = g_mod + (stream * 6 + shiftc) * DM;
    const float* sc = g_mod + (stream * 6 + scalec) * DM;
    __nv_bfloat16* yr = y + (size_t)row * DM;
    for (int c = tid; c < DM; c += 256) {
        yr[c] = __float2bfloat16_rn((xr[c] - mean) * inv * (1.0f + sc[c]) + sh[c]);
    }
}

// ---------------- bf16 tensor-core GEMM: C = epilogue(A@B) ----------------
// BM=128, BN=128, BK=32; 8 warps 2x4; warp tile 64x32; mma m16n8k16; cp.async 2-stage.
// A: [M][K] bf16.  Bw: [K/2][N] packed words.
// MODE 0: C = AB (+bias) fp32    MODE 1: C = resid + gate*(AB+bias) fp32
// MODE 2: C = gelu(AB+bias) -> bf16
template <int MODE, bool OBF16>
__global__ __launch_bounds__(256) void bgemm_kernel(
    const __nv_bfloat16* __restrict__ A, const unsigned* __restrict__ Bw,
    void* __restrict__ Cv, int M, int N, int K,
    const float* __restrict__ bias, const float* __restrict__ resid, int gidx) {
    __shared__ unsigned As[2][128][20];
    __shared__ unsigned Bs[2][16][136];

    int tid = threadIdx.x;
    int lane = tid & 31, warp = tid >> 5;
    int wm = warp >> 2, wn = warp & 3;          // 2 x 4 warp grid
    int g = lane >> 2, tg = lane & 3;
    int row0 = blockIdx.y * 128, col0 = blockIdx.x * 128;

    unsigned As_base = (unsigned)__cvta_generic_to_shared(&As[0][0][0]);
    unsigned Bs_base = (unsigned)__cvta_generic_to_shared(&Bs[0][0][0]);

    float acc[16][4];
#pragma unroll
    for (int i = 0; i < 16; i++)
#pragma unroll
        for (int j = 0; j < 4; j++) acc[i][j] = 0.0f;

    int T = K / 32;
    // prologue: stage 0
    {
#pragma unroll
        for (int i = 0; i < 2; i++) {
            int idx = tid + i * 256;
            int r = idx >> 2, cw = (idx & 3) * 4;          // A: 512 16B chunks
            cp_async16(As_base + ((0 * 128 + r) * 20 + cw) * 4,
                       &A[(size_t)(row0 + r) * K + 2 * cw]);
        }
#pragma unroll
        for (int i = 0; i < 2; i++) {
            int idx = tid + i * 256;
            int r = idx >> 5, cw = (idx & 31) * 4;         // B: 512 16B chunks
            cp_async16(Bs_base + ((0 * 16 + r) * 136 + cw) * 4,
                       &Bw[(size_t)r * N + col0 + cw]);
        }
        asm volatile("cp.async.commit_group;");
    }

    for (int t = 0; t < T; t++) {
        int s = t & 1;
        if (t + 1 < T) {
            int ns = (t + 1) & 1;
            int k0 = (t + 1) * 32;
#pragma unroll
            for (int i = 0; i < 2; i++) {
                int idx = tid + i * 256;
                int r = idx >> 2, cw = (idx & 3) * 4;
                cp_async16(As_base + ((ns * 128 + r) * 20 + cw) * 4,
                           &A[(size_t)(row0 + r) * K + k0 + 2 * cw]);
            }
#pragma unroll
            for (int i = 0; i < 2; i++) {
                int idx = tid + i * 256;
                int r = idx >> 5, cw = (idx & 31) * 4;
                cp_async16(Bs_base + ((ns * 16 + r) * 136 + cw) * 4,
                           &Bw[(size_t)(k0 / 2 + r) * N + col0 + cw]);
            }
            asm volatile("cp.async.commit_group;");
            asm volatile("cp.async.wait_group 1;");
        } else {
            asm volatile("cp.async.wait_group 0;");
        }
        __syncthreads();

#pragma unroll
        for (int k16 = 0; k16 < 2; k16++) {
            unsigned a[4][4], b[4][2];
#pragma unroll
            for (int mt = 0; mt < 4; mt++) {
                int r = wm * 64 + mt * 16;
                a[mt][0] = As[s][r + g][k16 * 8 + tg];
                a[mt][1] = As[s][r + 8 + g][k16 * 8 + tg];
                a[mt][2] = As[s][r + g][k16 * 8 + tg + 4];
                a[mt][3] = As[s][r + 8 + g][k16 * 8 + tg + 4];
            }
#pragma unroll
            for (int nt = 0; nt < 4; nt++) {
                int c = wn * 32 + nt * 8 + g;
                b[nt][0] = Bs[s][k16 * 8 + tg][c];
                b[nt][1] = Bs[s][k16 * 8 + tg + 4][c];
            }
#pragma unroll
            for (int mt = 0; mt < 4; mt++)
#pragma unroll
                for (int nt = 0; nt < 4; nt++)
                    mma_bf16(acc[mt * 4 + nt], a[mt], b[nt]);
        }
        __syncthreads();
    }

    const float* gate = (gidx >= 0) ? (g_mod + gidx * DM) : nullptr;
    float* Cf = (float*)Cv;
    __nv_bfloat16* Cb = (__nv_bfloat16*)Cv;
#pragma unroll
    for (int mt = 0; mt < 4; mt++) {
#pragma unroll
        for (int nt = 0; nt < 4; nt++) {
            int c = col0 + wn * 32 + nt * 8 + 2 * tg;
#pragma unroll
            for (int half = 0; half < 2; half++) {
                int r = row0 + wm * 64 + mt * 16 + g + half * 8;
#pragma unroll
                for (int jj = 0; jj < 2; jj++) {
                    int cc = c + jj;
                    float v = acc[mt * 4 + nt][half * 2 + jj];
                    if (bias) v += bias[cc];
                    if (MODE == 1) {
                        v = resid[(size_t)r * N + cc] + gate[cc] * v;
                    } else if (MODE == 2) {
                        float tt = v;
                        v = 0.5f * tt * (1.0f + tanhf(0.7978845608f * (tt + 0.044715f * tt * tt * tt)));
                    }
                    if (OBF16) Cb[(size_t)r * N + cc] = __float2bfloat16_rn(v);
                    else       Cf[(size_t)r * N + cc] = v;
                }
            }
        }
    }
}

// ---------------- qkv post: rmsnorm(q,k) + rope, scatter bf16 to [h][l][dh] ----------------
__global__ void qkv_post_kernel(const float* __restrict__ pe,
                                const float* __restrict__ oqs, const float* __restrict__ oks,
                                const float* __restrict__ cqs, const float* __restrict__ cks) {
    int gl = blockIdx.x;      // global token (cond first)
    int h = blockIdx.y;
    int d = threadIdx.x;      // 0..63
    bool is_cond = gl < LC;
    const float* src = is_cond ? (g_qkv + (size_t)LO * 3 * DM + (size_t)gl * 3 * DM)
                               : (g_qkv + (size_t)(gl - LC) * 3 * DM);
    const float* qs = is_cond ? cqs : oqs;
    const float* ks = is_cond ? cks : oks;
    float qv = src[h * DH + d];
    float kv = src[DM + h * DH + d];
    float vv = src[2 * DM + h * DH + d];
    float qss = qv * qv, kss = kv * kv;
#pragma unroll
    for (int off = 16; off > 0; off >>= 1) {
        qss += __shfl_xor_sync(0xffffffffu, qss, off);
        kss += __shfl_xor_sync(0xffffffffu, kss, off);
    }
    __shared__ float red[4];
    int w = d >> 5;
    if ((d & 31) == 0) { red[w] = qss; red[2 + w] = kss; }
    __syncthreads();
    qss = red[0] + red[1];
    kss = red[2] + red[3];
    float qn = qv * rsqrtf(qss * (1.0f / DH) + 1e-6f) * qs[d];
    float kn = kv * rsqrtf(kss * (1.0f / DH) + 1e-6f) * ks[d];
    __shared__ float sq[DH], sk[DH];
    sq[d] = qn; sk[d] = kn;
    __syncthreads();
    int p = d >> 1, j = d & 1;
    const float* pp = pe + (((size_t)gl * 32 + p) * 2 + j) * 2;
    float q0 = sq[2 * p], q1 = sq[2 * p + 1];
    float k0 = sk[2 * p], k1 = sk[2 * p + 1];
    float qo = pp[0] * q0 + pp[1] * q1;
    float ko = pp[0] * k0 + pp[1] * k1;
    size_t oidx = ((size_t)h * LT + gl) * DH + d;
    g_q[oidx] = __float2bfloat16_rn(qo * 0.125f);   // pre-scale by 1/sqrt(64)
    g_k[oidx] = __float2bfloat16_rn(ko);
    g_v[oidx] = __float2bfloat16_rn(vv);
}

// ---------------- attention: flash w/ bf16 mma, 128 q-rows/block, 64-key tiles ----------------
// 8 warps in 4x2 (wm: 32 q-rows, wn: 32 cols). mma m16n8k16.
// smem word offsets (u32 units):
#define A_QS   0                    // [128][36] packed Q words
#define A_KS   (128*36)             // [64][36] packed K words
#define A_VS   (A_KS + 64*36)       // [32][72] V packed by key-pair: [kp][d]
#define A_PF   (A_VS + 32*72)       // [128][68] fp32 scores
#define A_PS   (A_PF + 128*68)      // [128][36] packed P words
#define A_RM   (A_PS + 128*36)
#define A_RL   (A_RM + 128)
#define A_CS   (A_RL + 128)
#define A_TOTW (A_CS + 128)

__global__ __launch_bounds__(256, 2) void attn_mma_kernel() {
    extern __shared__ unsigned smu[];
    unsigned* Qs = smu + A_QS;
    unsigned* Ks = smu + A_KS;
    unsigned* Vs = smu + A_VS;
    float* Pf = (float*)(smu + A_PF);
    unsigned* Ps = smu + A_PS;
    float* row_m = (float*)(smu + A_RM);
    float* row_l = (float*)(smu + A_RL);
    float* corr_s = (float*)(smu + A_CS);

    int h = blockIdx.x;
    int q0 = blockIdx.y * 128;
    int tid = threadIdx.x;
    int lane = tid & 31, warp = tid >> 5;
    int wm = warp >> 1, wn = warp & 1;     // 4 x 2
    int g = lane >> 2, tg = lane & 3;

    const __nv_bfloat16* qb = g_q + ((size_t)h * LT + q0) * DH;
    const __nv_bfloat16* kb = g_k + (size_t)h * LT * DH;
    const __nv_bfloat16* vb = g_v + (size_t)h * LT * DH;

    // load Q tile: 128 rows x 64 bf16 = 8 chunks/row -> 1024 chunks
#pragma unroll
    for (int i = 0; i < 4; i++) {
        int idx = tid + i * 256;
        int r = idx >> 3, cw = (idx & 7) * 4;
        uint4 v = *(const uint4*)&qb[(size_t)r * DH + 2 * cw];
        *(uint4*)&Qs[r * 36 + cw] = v;
    }
    if (tid < 128) { row_m[tid] = -3e38f; row_l[tid] = 0.0f; }

    float acc_o[2][4][4];
#pragma unroll
    for (int mt = 0; mt < 2; mt++)
#pragma unroll
        for (int nt = 0; nt < 4; nt++)
#pragma unroll
            for (int j = 0; j < 4; j++) acc_o[mt][nt][j] = 0.0f;

    for (int kt = 0; kt < LT; kt += 64) {
        __syncthreads();   // prior iteration's PV reads of Vs/Ps done
        // K tile: 64 rows x 8 chunks = 512 chunks
#pragma unroll
        for (int i = 0; i < 2; i++) {
            int idx = tid + i * 256;
            int r = idx >> 3, cw = (idx & 7) * 4;
            uint4 v = *(const uint4*)&kb[(size_t)(kt + r) * DH + 2 * cw];
            *(uint4*)&Ks[r * 36 + cw] = v;
        }
        // V tile transposed-pack: 32 key-pairs x 8 d-groups = 256 tasks
        {
            int kp = tid >> 3, dg = tid & 7;
            int d0 = dg * 8;
            uint4 a4 = *(const uint4*)&vb[(size_t)(kt + 2 * kp) * DH + d0];
            uint4 b4 = *(const uint4*)&vb[(size_t)(kt + 2 * kp + 1) * DH + d0];
            unsigned o0 = __byte_perm(a4.x, b4.x, 0x5410);
            unsigned o1 = __byte_perm(a4.x, b4.x, 0x7632);
            unsigned o2 = __byte_perm(a4.y, b4.y, 0x5410);
            unsigned o3 = __byte_perm(a4.y, b4.y, 0x7632);
            unsigned o4 = __byte_perm(a4.z, b4.z, 0x5410);
            unsigned o5 = __byte_perm(a4.z, b4.z, 0x7632);
            unsigned o6 = __byte_perm(a4.w, b4.w, 0x5410);
            unsigned o7 = __byte_perm(a4.w, b4.w, 0x7632);
            *(uint4*)&Vs[kp * 72 + d0]     = make_uint4(o0, o1, o2, o3);
            *(uint4*)&Vs[kp * 72 + d0 + 4] = make_uint4(o4, o5, o6, o7);
        }
        __syncthreads();

        // ---- S = Q K^T : warp computes 32x32, 4 k16 steps over dh ----
        float acc_s[2][4][4];
#pragma unroll
        for (int mt = 0; mt < 2; mt++)
#pragma unroll
            for (int nt = 0; nt < 4; nt++)
#pragma unroll
                for (int j = 0; j < 4; j++) acc_s[mt][nt][j] = 0.0f;
#pragma unroll
        for (int k16 = 0; k16 < 4; k16++) {
            unsigned a[2][4], b[4][2];
#pragma unroll
            for (int mt = 0; mt < 2; mt++) {
                int r = wm * 32 + mt * 16;
                a[mt][0] = Qs[(r + g) * 36 + k16 * 8 + tg];
                a[mt][1] = Qs[(r + 8 + g) * 36 + k16 * 8 + tg];
                a[mt][2] = Qs[(r + g) * 36 + k16 * 8 + tg + 4];
                a[mt][3] = Qs[(r + 8 + g) * 36 + k16 * 8 + tg + 4];
            }
#pragma unroll
            for (int nt = 0; nt < 4; nt++) {
                int c = wn * 32 + nt * 8 + g;
                b[nt][0] = Ks[c * 36 + k16 * 8 + tg];
                b[nt][1] = Ks[c * 36 + k16 * 8 + tg + 4];
            }
#pragma unroll
            for (int mt = 0; mt < 2; mt++)
#pragma unroll
                for (int nt = 0; nt < 4; nt++)
                    mma_bf16(acc_s[mt][nt], a[mt], b[nt]);
        }
        // scatter S -> Pf (fp32)
#pragma unroll
        for (int mt = 0; mt < 2; mt++)
#pragma unroll
            for (int nt = 0; nt < 4; nt++)
#pragma unroll
                for (int half = 0; half < 2; half++) {
                    int r = wm * 32 + mt * 16 + half * 8 + g;
                    int c = wn * 32 + nt * 8 + 2 * tg;
                    Pf[r * 68 + c]     = acc_s[mt][nt][half * 2 + 0];
                    Pf[r * 68 + c + 1] = acc_s[mt][nt][half * 2 + 1];
                }
        __syncthreads();

        // ---- online softmax: 2 threads per row, 32 cols each; pack P to bf16 ----
        {
            int r = tid >> 1, halfc = tid & 1;
            float* prow = &Pf[r * 68 + halfc * 32];
            float mx = -3e38f;
#pragma unroll
            for (int c = 0; c < 32; c++) mx = fmaxf(mx, prow[c]);
            mx = fmaxf(mx, __shfl_xor_sync(0xffffffffu, mx, 1));
            float m_old = row_m[r];
            float m_new = fmaxf(m_old, mx);
            float corr = __expf(m_old - m_new);
            float ls = 0.0f;
            unsigned* pdst = &Ps[r * 36 + halfc * 16];
#pragma unroll
            for (int c = 0; c < 32; c += 2) {
                float p0 = __expf(prow[c] - m_new);
                float p1 = __expf(prow[c + 1] - m_new);
                ls += p0 + p1;
                pdst[c >> 1] = pack_bf16(p0, p1);
            }
            ls += __shfl_xor_sync(0xffffffffu, ls, 1);
            if (halfc == 0) {
                row_m[r] = m_new;
                row_l[r] = row_l[r] * corr + ls;
                corr_s[r] = corr;
            }
        }
        __syncthreads();

        // ---- rescale O, then O += P V (4 k16 steps over keys) ----
#pragma unroll
        for (int mt = 0; mt < 2; mt++)
#pragma unroll
            for (int half = 0; half < 2; half++) {
                float cr = corr_s[wm * 32 + mt * 16 + half * 8 + g];
#pragma unroll
                for (int nt = 0; nt < 4; nt++) {
                    acc_o[mt][nt][half * 2 + 0] *= cr;
                    acc_o[mt][nt][half * 2 + 1] *= cr;
                }
            }
#pragma unroll
        for (int k16 = 0; k16 < 4; k16++) {
            unsigned a[2][4], b[4][2];
#pragma unroll
            for (int mt = 0; mt < 2; mt++) {
                int r = wm * 32 + mt * 16;
                a[mt][0] = Ps[(r + g) * 36 + k16 * 8 + tg];
                a[mt][1] = Ps[(r + 8 + g) * 36 + k16 * 8 + tg];
                a[mt][2] = Ps[(r + g) * 36 + k16 * 8 + tg + 4];
                a[mt][3] = Ps[(r + 8 + g) * 36 + k16 * 8 + tg + 4];
            }
#pragma unroll
            for (int nt = 0; nt < 4; nt++) {
                int c = wn * 32 + nt * 8 + g;          // output col (d)
                b[nt][0] = Vs[(k16 * 8 + tg) * 72 + c];
                b[nt][1] = Vs[(k16 * 8 + tg + 4) * 72 + c];
            }
#pragma unroll
            for (int mt = 0; mt < 2; mt++)
#pragma unroll
                for (int nt = 0; nt < 4; nt++)
                    mma_bf16(acc_o[mt][nt], a[mt], b[nt]);
        }
    }
    __syncthreads();

    // epilogue: normalize by row_l, write bf16
#pragma unroll
    for (int mt = 0; mt < 2; mt++)
#pragma unroll
        for (int half = 0; half < 2; half++) {
            int r = wm * 32 + mt * 16 + half * 8 + g;
            float inv = 1.0f / row_l[r];
#pragma unroll
            for (int nt = 0; nt < 4; nt++) {
                int c = wn * 32 + nt * 8 + 2 * tg;
                __nv_bfloat162 v2;
                v2.x = __float2bfloat16_rn(acc_o[mt][nt][half * 2 + 0] * inv);
                v2.y = __float2bfloat16_rn(acc_o[mt][nt][half * 2 + 1] * inv);
                *(__nv_bfloat162*)&g_attn[(size_t)(q0 + r) * DM + h * DH + c] = v2;
            }
        }
}

// ---------------- launch ----------------
extern "C" void kernel_launch(void* const* d_in, const int* in_sizes, int n_in,
                              void* d_out, int out_size) {
    const float* obs   = (const float*)d_in[0];
    const float* cond  = (const float*)d_in[1];
    const float* vec   = (const float*)d_in[2];
    const float* pe    = (const float*)d_in[3];
    const float* o_mod_w = (const float*)d_in[4];
    const float* o_mod_b = (const float*)d_in[5];
    const float* o_qkv_w = (const float*)d_in[6];
    const float* o_q_s   = (const float*)d_in[7];
    const float* o_k_s   = (const float*)d_in[8];
    const float* o_proj_w = (const float*)d_in[9];
    const float* o_proj_b = (const float*)d_in[10];
    const float* o_mlp_w1 = (const float*)d_in[11];
    const float* o_mlp_b1 = (const float*)d_in[12];
    const float* o_mlp_w2 = (const float*)d_in[13];
    const float* o_mlp_b2 = (const float*)d_in[14];
    const float* c_mod_w = (const float*)d_in[15];
    const float* c_mod_b = (const float*)d_in[16];
    const float* c_qkv_w = (const float*)d_in[17];
    const float* c_q_s   = (const float*)d_in[18];
    const float* c_k_s   = (const float*)d_in[19];
    const float* c_proj_w = (const float*)d_in[20];
    const float* c_proj_b = (const float*)d_in[21];
    const float* c_mlp_w1 = (const float*)d_in[22];
    const float* c_mlp_b1 = (const float*)d_in[23];
    const float* c_mlp_w2 = (const float*)d_in[24];
    const float* c_mlp_b2 = (const float*)d_in[25];

    float* out = (float*)d_out;
    float* out_obs = out;
    float* out_cond = out + (size_t)LO * DM;

    float *p_qkv;
    __nv_bfloat16 *p_xm, *p_attn, *p_h;
    unsigned* p_wb;
    cudaGetSymbolAddress((void**)&p_qkv, g_qkv);
    cudaGetSymbolAddress((void**)&p_xm, g_xm);
    cudaGetSymbolAddress((void**)&p_attn, g_attn);
    cudaGetSymbolAddress((void**)&p_h, g_h);
    cudaGetSymbolAddress((void**)&p_wb, g_wb);

    int attn_smem = A_TOTW * 4;
    static int init = 0;
    if (!init) {
        init = 1;
        cudaFuncSetAttribute(attn_mma_kernel, cudaFuncAttributeMaxDynamicSharedMemorySize, attn_smem);
    }

    // 0. pack weights to bf16 pair-words
    cvt_w_kernel<<<512 * 3072 / 256, 256>>>(o_qkv_w, p_wb + W_OQKV, 512, 3072);
    cvt_w_kernel<<<512 * 3072 / 256, 256>>>(c_qkv_w, p_wb + W_CQKV, 512, 3072);
    cvt_w_kernel<<<512 * 1024 / 256, 256>>>(o_proj_w, p_wb + W_OPROJ, 512, 1024);
    cvt_w_kernel<<<512 * 1024 / 256, 256>>>(c_proj_w, p_wb + W_CPROJ, 512, 1024);
    cvt_w_kernel<<<512 * 4096 / 256, 256>>>(o_mlp_w1, p_wb + W_OMLP1, 512, 4096);
    cvt_w_kernel<<<512 * 4096 / 256, 256>>>(c_mlp_w1, p_wb + W_CMLP1, 512, 4096);
    cvt_w_kernel<<<2048 * 1024 / 256, 256>>>(o_mlp_w2, p_wb + W_OMLP2, 2048, 1024);
    cvt_w_kernel<<<2048 * 1024 / 256, 256>>>(c_mlp_w2, p_wb + W_CMLP2, 2048, 1024);

    // 1. modulation vectors
    mod_kernel<<<48, 256>>>(vec, o_mod_w, o_mod_b, c_mod_w, c_mod_b);

    // 2. LN + mod (0=shift1, 1=scale1) -> bf16 xm
    ln_mod_kernel<<<LO, 256>>>(obs, p_xm, 0, 0, 1);
    ln_mod_kernel<<<LC, 256>>>(cond, p_xm + (size_t)LO * DM, 1, 0, 1);

    // 3. qkv GEMMs -> fp32 g_qkv
    {
        dim3 g(3 * DM / 128, LO / 128);
        bgemm_kernel<0, false><<<g, 256>>>(p_xm, p_wb + W_OQKV, p_qkv, LO, 3 * DM, DM,
                                           nullptr, nullptr, -1);
    }
    {
        dim3 g(3 * DM / 128, LC / 128);
        bgemm_kernel<0, false><<<g, 256>>>(p_xm + (size_t)LO * DM, p_wb + W_CQKV,
                                           p_qkv + (size_t)LO * 3 * DM, LC, 3 * DM, DM,
                                           nullptr, nullptr, -1);
    }

    // 4. rmsnorm + rope + scatter bf16
    {
        dim3 g(LT, NH);
        qkv_post_kernel<<<g, 64>>>(pe, o_q_s, o_k_s, c_q_s, c_k_s);
    }

    // 5. attention (bf16 tensor-core flash)
    {
        dim3 g(NH, LT / 128);
        attn_mma_kernel<<<g, 256, attn_smem>>>();
    }

    // 6. proj + gated residual (gate1 = chunk 2) -> fp32 d_out
    {
        dim3 g(DM / 128, LO / 128);
        bgemm_kernel<1, false><<<g, 256>>>(p_attn + (size_t)LC * DM, p_wb + W_OPROJ, out_obs,
                                           LO, DM, DM, o_proj_b, obs, 0 * 6 + 2);
    }
    {
        dim3 g(DM / 128, LC / 128);
        bgemm_kernel<1, false><<<g, 256>>>(p_attn, p_wb + W_CPROJ, out_cond,
                                           LC, DM, DM, c_proj_b, cond, 1 * 6 + 2);
    }

    // 7. LN2 + mod (3=shift2, 4=scale2) -> bf16 xm
    ln_mod_kernel<<<LO, 256>>>(out_obs, p_xm, 0, 3, 4);
    ln_mod_kernel<<<LC, 256>>>(out_cond, p_xm + (size_t)LO * DM, 1, 3, 4);

    // 8. mlp1 + gelu -> bf16 g_h
    {
        dim3 g(MH / 128, LO / 128);
        bgemm_kernel<2, true><<<g, 256>>>(p_xm, p_wb + W_OMLP1, p_h, LO, MH, DM,
                                          o_mlp_b1, nullptr, -1);
    }
    {
        dim3 g(MH / 128, LC / 128);
        bgemm_kernel<2, true><<<g, 256>>>(p_xm + (size_t)LO * DM, p_wb + W_CMLP1,
                                          p_h + (size_t)LO * MH, LC, MH, DM,
                                          c_mlp_b1, nullptr, -1);
    }

    // 9. mlp2 + gated residual (gate2 = chunk 5) -> fp32 d_out (in-place residual)
    {
        dim3 g(DM / 128, LO / 128);
        bgemm_kernel<1, false><<<g, 256>>>(p_h, p_wb + W_OMLP2, out_obs, LO, DM, MH,
                                           o_mlp_b2, out_obs, 0 * 6 + 5);
    }
    {
        dim3 g(DM / 128, LC / 128);
        bgemm_kernel<1, false><<<g, 256>>>(p_h + (size_t)LO * MH, p_wb + W_CMLP2, out_cond,
                                           LC, DM, MH, c_mlp_b2, out_cond, 1 * 6 + 5);
    }
}

// round 9
// speedup vs baseline: 1.2384x; 1.2384x over previous
#include <cuda_runtime.h>
#include <cuda_bf16.h>
#include <math.h>

#define LO 3072
#define LC 1024
#define LT 4096   // LO + LC
#define DM 1024   // model dim
#define NH 16
#define DH 64
#define MH 4096

// ---------------- scratch (device globals; no allocation allowed) ----------------
__device__ float g_mod[12 * DM];          // [2 streams][6 chunks][1024]
__device__ float g_xm[LT * DM];           // modulated LN output (obs rows 0..LO-1, cond at LO)
__device__ float g_qkv[LT * 3 * DM];      // raw qkv (obs rows at 0, cond rows at LO*3*DM)
__device__ unsigned g_q[NH * LT * DH];    // [h][l][dh] tf32 words, q pre-scaled by 0.125
__device__ unsigned g_k[NH * LT * DH];    // tf32 words
__device__ unsigned g_v[NH * LT * DH];    // tf32 words
__device__ float g_attn[LT * DM];         // attention out fp32, global l order
__device__ float g_h[LT * MH];            // mlp hidden

// ---------------- helpers ----------------
__device__ __forceinline__ unsigned f2tf(float f) {
    unsigned u;
    asm("cvt.rna.tf32.f32 %0, %1;" : "=r"(u) : "f"(f));
    return u;
}

__device__ __forceinline__ void mma_tf32(float d[4], const unsigned a[4], const unsigned b[2]) {
    asm volatile(
        "mma.sync.aligned.m16n8k8.row.col.f32.tf32.tf32.f32 "
        "{%0,%1,%2,%3}, {%4,%5,%6,%7}, {%8,%9}, {%0,%1,%2,%3};"
        : "+f"(d[0]), "+f"(d[1]), "+f"(d[2]), "+f"(d[3])
        : "r"(a[0]), "r"(a[1]), "r"(a[2]), "r"(a[3]), "r"(b[0]), "r"(b[1]));
}

// ---------------- modulation: silu(vec) @ mod_w + mod_b (K-split, 192 blocks) ----------------
__global__ __launch_bounds__(256) void mod_kernel(
    const float* __restrict__ vec,
    const float* __restrict__ ow, const float* __restrict__ ob,
    const float* __restrict__ cw, const float* __restrict__ cb) {
    __shared__ float sv[DM];
    __shared__ float part[256];
    int tid = threadIdx.x;
    for (int i = tid; i < DM; i += 256) {
        float v = vec[i];
        sv[i] = v / (1.0f + expf(-v));
    }
    __syncthreads();
    int j0 = blockIdx.x * 64;                 // 0..12287 step 64
    int stream = j0 / (6 * DM);
    int jbase = j0 % (6 * DM);
    int jl = tid & 63;
    int kc = tid >> 6;                        // 0..3
    int jj = jbase + jl;
    const float* w = stream ? cw : ow;
    const float* wp = w + (size_t)(kc * 256) * (6 * DM) + jj;
    const float* svp = sv + kc * 256;
    float acc = 0.0f;
#pragma unroll 8
    for (int k = 0; k < 256; k++)
        acc += svp[k] * wp[(size_t)k * (6 * DM)];
    part[tid] = acc;
    __syncthreads();
    if (kc == 0) {
        const float* b = stream ? cb : ob;
        float s = part[tid] + part[tid + 64] + part[tid + 128] + part[tid + 192];
        g_mod[stream * 6 * DM + jbase + jl] = s + b[jj];
    }
}

// ---------------- layernorm + modulation, merged obs/cond ----------------
__global__ void ln_mod_kernel(const float* __restrict__ x1, const float* __restrict__ x2,
                              float* __restrict__ y, int shiftc, int scalec) {
    int row = blockIdx.x;
    int tid = threadIdx.x;
    int stream = (row >= LO);
    const float* xr = stream ? (x2 + (size_t)(row - LO) * DM) : (x1 + (size_t)row * DM);
    __shared__ float r1[256], r2[256];
    float s = 0.0f, ss = 0.0f;
    for (int c = tid; c < DM; c += 256) {
        float v = xr[c];
        s += v; ss += v * v;
    }
    r1[tid] = s; r2[tid] = ss;
    __syncthreads();
    for (int st = 128; st > 0; st >>= 1) {
        if (tid < st) { r1[tid] += r1[tid + st]; r2[tid] += r2[tid + st]; }
        __syncthreads();
    }
    float mean = r1[0] * (1.0f / DM);
    float var = r2[0] * (1.0f / DM) - mean * mean;
    float inv = rsqrtf(var + 1e-6f);
    const float* sh = g_mod + (stream * 6 + shiftc) * DM;
    const float* sc = g_mod + (stream * 6 + scalec) * DM;
    float* yr = y + (size_t)row * DM;
    for (int c = tid; c < DM; c += 256) {
        yr[c] = (xr[c] - mean) * inv * (1.0f + sc[c]) + sh[c];
    }
}

// ---------------- tf32 tensor-core GEMM, merged obs/cond pair ----------------
// BM=128, BN=128, BK=32; 8 warps in 2x4; warp tile 64x32; mma m16n8k8.
// mode 0: C = AB (+bias)    mode 1: C = resid + gate*(AB + bias)
// mode 2: C = gelu_tanh(AB + bias)
__global__ __launch_bounds__(256) void mma_gemm2_kernel(
    const float* __restrict__ A1, const float* __restrict__ B1, float* __restrict__ C1,
    const float* __restrict__ A2, const float* __restrict__ B2, float* __restrict__ C2,
    int M1, int N, int K,
    const float* __restrict__ bias1, const float* __restrict__ bias2,
    const float* __restrict__ resid1, const float* __restrict__ resid2,
    int gidx1, int gidx2, int mode) {
    __shared__ unsigned As[128][36];   // row-major, pad 4
    __shared__ unsigned Bs[32][136];   // k-major,   pad 8

    int tid = threadIdx.x;
    int lane = tid & 31, warp = tid >> 5;
    int wm = warp >> 2, wn = warp & 3;          // 2 x 4 warp grid
    int g = lane >> 2, tg = lane & 3;
    int by = blockIdx.y * 128, col0 = blockIdx.x * 128;

    const float *A, *B, *bias, *resid;
    float* C;
    int gidx, row0;
    if (by < M1) { A = A1; B = B1; C = C1; bias = bias1; resid = resid1; gidx = gidx1; row0 = by; }
    else         { A = A2; B = B2; C = C2; bias = bias2; resid = resid2; gidx = gidx2; row0 = by - M1; }

    float acc[16][4];
#pragma unroll
    for (int i = 0; i < 16; i++)
#pragma unroll
        for (int j = 0; j < 4; j++) acc[i][j] = 0.0f;

    for (int k0 = 0; k0 < K; k0 += 32) {
#pragma unroll
        for (int i = 0; i < 4; i++) {
            int idx = tid + i * 256;
            int r = idx >> 3, c4 = (idx & 7) << 2;
            float4 v = *(const float4*)&A[(size_t)(row0 + r) * K + k0 + c4];
            As[r][c4 + 0] = f2tf(v.x); As[r][c4 + 1] = f2tf(v.y);
            As[r][c4 + 2] = f2tf(v.z); As[r][c4 + 3] = f2tf(v.w);
        }
#pragma unroll
        for (int i = 0; i < 4; i++) {
            int idx = tid + i * 256;
            int r = idx >> 5, c4 = (idx & 31) << 2;
            float4 v = *(const float4*)&B[(size_t)(k0 + r) * N + col0 + c4];
            Bs[r][c4 + 0] = f2tf(v.x); Bs[r][c4 + 1] = f2tf(v.y);
            Bs[r][c4 + 2] = f2tf(v.z); Bs[r][c4 + 3] = f2tf(v.w);
        }
        __syncthreads();
#pragma unroll
        for (int k8 = 0; k8 < 4; k8++) {
            unsigned a[4][4], b[4][2];
#pragma unroll
            for (int mt = 0; mt < 4; mt++) {
                int r = wm * 64 + mt * 16;
                a[mt][0] = As[r + g][k8 * 8 + tg];
                a[mt][1] = As[r + 8 + g][k8 * 8 + tg];
                a[mt][2] = As[r + g][k8 * 8 + tg + 4];
                a[mt][3] = As[r + 8 + g][k8 * 8 + tg + 4];
            }
#pragma unroll
            for (int nt = 0; nt < 4; nt++) {
                int c = wn * 32 + nt * 8 + g;
                b[nt][0] = Bs[k8 * 8 + tg][c];
                b[nt][1] = Bs[k8 * 8 + tg + 4][c];
            }
#pragma unroll
            for (int mt = 0; mt < 4; mt++)
#pragma unroll
                for (int nt = 0; nt < 4; nt++)
                    mma_tf32(acc[mt * 4 + nt], a[mt], b[nt]);
        }
        __syncthreads();
    }

    const float* gate = (gidx >= 0) ? (g_mod + gidx * DM) : nullptr;
#pragma unroll
    for (int mt = 0; mt < 4; mt++) {
#pragma unroll
        for (int nt = 0; nt < 4; nt++) {
            int c = col0 + wn * 32 + nt * 8 + 2 * tg;
#pragma unroll
            for (int half = 0; half < 2; half++) {
                int r = row0 + wm * 64 + mt * 16 + g + half * 8;
#pragma unroll
                for (int jj = 0; jj < 2; jj++) {
                    int cc = c + jj;
                    float v = acc[mt * 4 + nt][half * 2 + jj];
                    if (bias) v += bias[cc];
                    if (mode == 1) {
                        v = resid[(size_t)r * N + cc] + gate[cc] * v;
                    } else if (mode == 2) {
                        float t = v;
                        v = 0.5f * t * (1.0f + tanhf(0.7978845608f * (t + 0.044715f * t * t * t)));
                    }
                    C[(size_t)r * N + cc] = v;
                }
            }
        }
    }
}

// ---------------- qkv post: rmsnorm(q,k) + rope, scatter tf32 words to [h][l][dh] ----------------
__global__ void qkv_post_kernel(const float* __restrict__ pe,
                                const float* __restrict__ oqs, const float* __restrict__ oks,
                                const float* __restrict__ cqs, const float* __restrict__ cks) {
    int gl = blockIdx.x;      // global token (cond first)
    int h = blockIdx.y;
    int d = threadIdx.x;      // 0..63
    bool is_cond = gl < LC;
    const float* src = is_cond ? (g_qkv + (size_t)LO * 3 * DM + (size_t)gl * 3 * DM)
                               : (g_qkv + (size_t)(gl - LC) * 3 * DM);
    const float* qs = is_cond ? cqs : oqs;
    const float* ks = is_cond ? cks : oks;
    float qv = src[h * DH + d];
    float kv = src[DM + h * DH + d];
    float vv = src[2 * DM + h * DH + d];
    float qss = qv * qv, kss = kv * kv;
#pragma unroll
    for (int off = 16; off > 0; off >>= 1) {
        qss += __shfl_xor_sync(0xffffffffu, qss, off);
        kss += __shfl_xor_sync(0xffffffffu, kss, off);
    }
    __shared__ float red[4];
    int w = d >> 5;
    if ((d & 31) == 0) { red[w] = qss; red[2 + w] = kss; }
    __syncthreads();
    qss = red[0] + red[1];
    kss = red[2] + red[3];
    float qn = qv * rsqrtf(qss * (1.0f / DH) + 1e-6f) * qs[d];
    float kn = kv * rsqrtf(kss * (1.0f / DH) + 1e-6f) * ks[d];
    __shared__ float sq[DH], sk[DH];
    sq[d] = qn; sk[d] = kn;
    __syncthreads();
    int p = d >> 1, j = d & 1;
    const float* pp = pe + (((size_t)gl * 32 + p) * 2 + j) * 2;
    float q0 = sq[2 * p], q1 = sq[2 * p + 1];
    float k0 = sk[2 * p], k1 = sk[2 * p + 1];
    float qo = pp[0] * q0 + pp[1] * q1;
    float ko = pp[0] * k0 + pp[1] * k1;
    size_t oidx = ((size_t)h * LT + gl) * DH + d;
    g_q[oidx] = f2tf(qo * 0.125f);   // pre-scale by 1/sqrt(64), pre-convert to tf32
    g_k[oidx] = f2tf(ko);
    g_v[oidx] = f2tf(vv);
}

// ---------------- attention: flash w/ tf32 mma, 128 q-rows/block, 64-key tiles ----------------
// 8 warps in 4x2 (wm: 32 q-rows each, wn: 32 cols each). mma m16n8k8.
#define AS 68   // padded row stride (u32 words)
__global__ __launch_bounds__(256, 2) void attn_mma_kernel() {
    extern __shared__ unsigned smu[];
    unsigned* Qs = smu;                    // [128][AS] tf32
    unsigned* Ks = Qs + 128 * AS;          // [64][AS]  tf32
    unsigned* Vs = Ks + 64 * AS;           // [64][AS]  tf32
    float* Ps = (float*)(Vs + 64 * AS);    // [128][AS] fp32 scores
    float* row_m = Ps + 128 * AS;          // [128]
    float* row_l = row_m + 128;            // [128]
    float* corr_s = row_l + 128;           // [128]

    int h = blockIdx.x;
    int q0 = blockIdx.y * 128;
    int tid = threadIdx.x;
    int lane = tid & 31, warp = tid >> 5;
    int wm = warp >> 1, wn = warp & 1;     // 4 x 2
    int g = lane >> 2, tg = lane & 3;

    const unsigned* qb = g_q + ((size_t)h * LT + q0) * DH;
    const unsigned* kb = g_k + (size_t)h * LT * DH;
    const unsigned* vb = g_v + (size_t)h * LT * DH;

    // load Q tile: 128 rows x 64 words = 2048 uint4 slots
#pragma unroll
    for (int i = 0; i < 8; i++) {
        int idx = tid + i * 256;
        int r = idx >> 4, c = (idx & 15) << 2;
        *(uint4*)&Qs[r * AS + c] = *(const uint4*)&qb[(size_t)r * DH + c];
    }
    if (tid < 128) { row_m[tid] = -3e38f; row_l[tid] = 0.0f; }

    float acc_o[2][4][4];
#pragma unroll
    for (int mt = 0; mt < 2; mt++)
#pragma unroll
        for (int nt = 0; nt < 4; nt++)
#pragma unroll
            for (int j = 0; j < 4; j++) acc_o[mt][nt][j] = 0.0f;

    for (int kt = 0; kt < LT; kt += 64) {
        __syncthreads();   // prior iteration's PV reads of Vs/Ps done
        // load K,V tiles: 64 rows x 64 words = 1024 uint4 slots each
#pragma unroll
        for (int i = 0; i < 4; i++) {
            int idx = tid + i * 256;
            int r = idx >> 4, c = (idx & 15) << 2;
            *(uint4*)&Ks[r * AS + c] = *(const uint4*)&kb[(size_t)(kt + r) * DH + c];
            *(uint4*)&Vs[r * AS + c] = *(const uint4*)&vb[(size_t)(kt + r) * DH + c];
        }
        __syncthreads();

        // ---- S = Q K^T : warp computes 32x32 ----
        float acc_s[2][4][4];
#pragma unroll
        for (int mt = 0; mt < 2; mt++)
#pragma unroll
            for (int nt = 0; nt < 4; nt++)
#pragma unroll
                for (int j = 0; j < 4; j++) acc_s[mt][nt][j] = 0.0f;
#pragma unroll
        for (int k8 = 0; k8 < 8; k8++) {
            unsigned a[2][4], b[4][2];
#pragma unroll
            for (int mt = 0; mt < 2; mt++) {
                int r = wm * 32 + mt * 16;
                a[mt][0] = Qs[(r + g) * AS + k8 * 8 + tg];
                a[mt][1] = Qs[(r + 8 + g) * AS + k8 * 8 + tg];
                a[mt][2] = Qs[(r + g) * AS + k8 * 8 + tg + 4];
                a[mt][3] = Qs[(r + 8 + g) * AS + k8 * 8 + tg + 4];
            }
#pragma unroll
            for (int nt = 0; nt < 4; nt++) {
                int c = wn * 32 + nt * 8 + g;
                b[nt][0] = Ks[c * AS + k8 * 8 + tg];
                b[nt][1] = Ks[c * AS + k8 * 8 + tg + 4];
            }
#pragma unroll
            for (int mt = 0; mt < 2; mt++)
#pragma unroll
                for (int nt = 0; nt < 4; nt++)
                    mma_tf32(acc_s[mt][nt], a[mt], b[nt]);
        }
        // scatter S -> Ps (fp32)
#pragma unroll
        for (int mt = 0; mt < 2; mt++)
#pragma unroll
            for (int nt = 0; nt < 4; nt++)
#pragma unroll
                for (int half = 0; half < 2; half++) {
                    int r = wm * 32 + mt * 16 + half * 8 + g;
                    int c = wn * 32 + nt * 8 + 2 * tg;
                    Ps[r * AS + c]     = acc_s[mt][nt][half * 2 + 0];
                    Ps[r * AS + c + 1] = acc_s[mt][nt][half * 2 + 1];
                }
        __syncthreads();

        // ---- online softmax: 2 threads per row, 32 cols each ----
        {
            int r = tid >> 1, halfc = tid & 1;
            float* prow = &Ps[r * AS + halfc * 32];
            float mx = -3e38f;
#pragma unroll
            for (int c = 0; c < 32; c++) mx = fmaxf(mx, prow[c]);
            mx = fmaxf(mx, __shfl_xor_sync(0xffffffffu, mx, 1));
            float m_old = row_m[r];
            float m_new = fmaxf(m_old, mx);
            float corr = __expf(m_old - m_new);
            float ls = 0.0f;
#pragma unroll
            for (int c = 0; c < 32; c++) {
                float p = __expf(prow[c] - m_new);
                prow[c] = p;
                ls += p;
            }
            ls += __shfl_xor_sync(0xffffffffu, ls, 1);
            if (halfc == 0) {
                row_m[r] = m_new;
                row_l[r] = row_l[r] * corr + ls;
                corr_s[r] = corr;
            }
        }
        __syncthreads();

        // ---- rescale O, then O += P V ----
#pragma unroll
        for (int mt = 0; mt < 2; mt++)
#pragma unroll
            for (int half = 0; half < 2; half++) {
                float cr = corr_s[wm * 32 + mt * 16 + half * 8 + g];
#pragma unroll
                for (int nt = 0; nt < 4; nt++) {
                    acc_o[mt][nt][half * 2 + 0] *= cr;
                    acc_o[mt][nt][half * 2 + 1] *= cr;
                }
            }
#pragma unroll
        for (int k8 = 0; k8 < 8; k8++) {
            unsigned a[2][4], b[4][2];
#pragma unroll
            for (int mt = 0; mt < 2; mt++) {
                int r = wm * 32 + mt * 16;
                a[mt][0] = f2tf(Ps[(r + g) * AS + k8 * 8 + tg]);
                a[mt][1] = f2tf(Ps[(r + 8 + g) * AS + k8 * 8 + tg]);
                a[mt][2] = f2tf(Ps[(r + g) * AS + k8 * 8 + tg + 4]);
                a[mt][3] = f2tf(Ps[(r + 8 + g) * AS + k8 * 8 + tg + 4]);
            }
#pragma unroll
            for (int nt = 0; nt < 4; nt++) {
                int c = wn * 32 + nt * 8 + g;          // output col (d)
                b[nt][0] = Vs[(k8 * 8 + tg) * AS + c];
                b[nt][1] = Vs[(k8 * 8 + tg + 4) * AS + c];
            }
#pragma unroll
            for (int mt = 0; mt < 2; mt++)
#pragma unroll
                for (int nt = 0; nt < 4; nt++)
                    mma_tf32(acc_o[mt][nt], a[mt], b[nt]);
        }
    }
    __syncthreads();

    // epilogue: normalize by row_l, write out
#pragma unroll
    for (int mt = 0; mt < 2; mt++)
#pragma unroll
        for (int half = 0; half < 2; half++) {
            int r = wm * 32 + mt * 16 + half * 8 + g;
            float inv = 1.0f / row_l[r];
#pragma unroll
            for (int nt = 0; nt < 4; nt++) {
                int c = wn * 32 + nt * 8 + 2 * tg;
                float* dst = &g_attn[(size_t)(q0 + r) * DM + h * DH + c];
                dst[0] = acc_o[mt][nt][half * 2 + 0] * inv;
                dst[1] = acc_o[mt][nt][half * 2 + 1] * inv;
            }
        }
}

// ---------------- launch ----------------
extern "C" void kernel_launch(void* const* d_in, const int* in_sizes, int n_in,
                              void* d_out, int out_size) {
    const float* obs   = (const float*)d_in[0];
    const float* cond  = (const float*)d_in[1];
    const float* vec   = (const float*)d_in[2];
    const float* pe    = (const float*)d_in[3];
    const float* o_mod_w = (const float*)d_in[4];
    const float* o_mod_b = (const float*)d_in[5];
    const float* o_qkv_w = (const float*)d_in[6];
    const float* o_q_s   = (const float*)d_in[7];
    const float* o_k_s   = (const float*)d_in[8];
    const float* o_proj_w = (const float*)d_in[9];
    const float* o_proj_b = (const float*)d_in[10];
    const float* o_mlp_w1 = (const float*)d_in[11];
    const float* o_mlp_b1 = (const float*)d_in[12];
    const float* o_mlp_w2 = (const float*)d_in[13];
    const float* o_mlp_b2 = (const float*)d_in[14];
    const float* c_mod_w = (const float*)d_in[15];
    const float* c_mod_b = (const float*)d_in[16];
    const float* c_qkv_w = (const float*)d_in[17];
    const float* c_q_s   = (const float*)d_in[18];
    const float* c_k_s   = (const float*)d_in[19];
    const float* c_proj_w = (const float*)d_in[20];
    const float* c_proj_b = (const float*)d_in[21];
    const float* c_mlp_w1 = (const float*)d_in[22];
    const float* c_mlp_b1 = (const float*)d_in[23];
    const float* c_mlp_w2 = (const float*)d_in[24];
    const float* c_mlp_b2 = (const float*)d_in[25];

    float* out = (float*)d_out;
    float* out_obs = out;                 // rows 0..LO-1
    float* out_cond = out + (size_t)LO * DM;

    float *p_xm, *p_qkv, *p_attn, *p_h;
    cudaGetSymbolAddress((void**)&p_xm, g_xm);
    cudaGetSymbolAddress((void**)&p_qkv, g_qkv);
    cudaGetSymbolAddress((void**)&p_attn, g_attn);
    cudaGetSymbolAddress((void**)&p_h, g_h);

    int smem_bytes = (int)((384 * AS) * 4 + 3 * 128 * 4);
    static int init = 0;
    if (!init) {
        init = 1;
        cudaFuncSetAttribute(attn_mma_kernel, cudaFuncAttributeMaxDynamicSharedMemorySize, smem_bytes);
    }

    // 1. modulation vectors (K-split for parallelism)
    mod_kernel<<<192, 256>>>(vec, o_mod_w, o_mod_b, c_mod_w, c_mod_b);

    // 2. LN + mod (chunks: 0=shift1, 1=scale1), merged
    ln_mod_kernel<<<LT, 256>>>(obs, cond, p_xm, 0, 1);

    // 3. qkv GEMMs, merged
    {
        dim3 g(3 * DM / 128, LT / 128);
        mma_gemm2_kernel<<<g, 256>>>(p_xm, o_qkv_w, p_qkv,
                                     p_xm + (size_t)LO * DM, c_qkv_w, p_qkv + (size_t)LO * 3 * DM,
                                     LO, 3 * DM, DM,
                                     nullptr, nullptr, nullptr, nullptr, -1, -1, 0);
    }

    // 4. rmsnorm + rope + scatter (tf32 pre-converted)
    {
        dim3 g(LT, NH);
        qkv_post_kernel<<<g, 64>>>(pe, o_q_s, o_k_s, c_q_s, c_k_s);
    }

    // 5. attention (tensor-core flash)
    {
        dim3 g(NH, LT / 128);
        attn_mma_kernel<<<g, 256, smem_bytes>>>();
    }

    // 6. proj + gated residual (gate1 = chunk 2), merged
    {
        dim3 g(DM / 128, LT / 128);
        mma_gemm2_kernel<<<g, 256>>>(p_attn + (size_t)LC * DM, o_proj_w, out_obs,
                                     p_attn, c_proj_w, out_cond,
                                     LO, DM, DM,
                                     o_proj_b, c_proj_b, obs, cond, 0 * 6 + 2, 1 * 6 + 2, 1);
    }

    // 7. LN2 + mod (chunks: 3=shift2, 4=scale2), merged
    ln_mod_kernel<<<LT, 256>>>(out_obs, out_cond, p_xm, 3, 4);

    // 8. mlp1 + gelu, merged
    {
        dim3 g(MH / 128, LT / 128);
        mma_gemm2_kernel<<<g, 256>>>(p_xm, o_mlp_w1, p_h,
                                     p_xm + (size_t)LO * DM, c_mlp_w1, p_h + (size_t)LO * MH,
                                     LO, MH, DM,
                                     o_mlp_b1, c_mlp_b1, nullptr, nullptr, -1, -1, 2);
    }

    // 9. mlp2 + gated residual (gate2 = chunk 5), merged, in-place residual on d_out
    {
        dim3 g(DM / 128, LT / 128);
        mma_gemm2_kernel<<<g, 256>>>(p_h, o_mlp_w2, out_obs,
                                     p_h + (size_t)LO * MH, c_mlp_w2, out_cond,
                                     LO, DM, MH,
                                     o_mlp_b2, c_mlp_b2, out_obs, out_cond, 0 * 6 + 5, 1 * 6 + 5, 1);
    }
}

// round 11
// speedup vs baseline: 1.2912x; 1.0426x over previous
#include <cuda_runtime.h>
#include <cuda_bf16.h>
#include <math.h>

#define LO 3072
#define LC 1024
#define LT 4096   // LO + LC
#define DM 1024   // model dim
#define NH 16
#define DH 64
#define MH 4096

// ---------------- scratch (device globals; no allocation allowed) ----------------
__device__ float g_mod[12 * DM];          // [2 streams][6 chunks][1024]
__device__ float g_xm[LT * DM];           // modulated LN output (obs rows 0..LO-1, cond at LO)
__device__ float g_qkv[LT * 3 * DM];      // raw qkv (obs rows at 0, cond rows at LO*3*DM)
__device__ unsigned g_q[NH * LT * DH];    // [h][l][dh] tf32 words, q pre-scaled by 0.125
__device__ unsigned g_k[NH * LT * DH];    // tf32 words
__device__ unsigned g_v[NH * LT * DH];    // tf32 words
__device__ float g_attn[LT * DM];         // attention out fp32, global l order
__device__ float g_h[LT * MH];            // mlp hidden

// ---------------- helpers ----------------
__device__ __forceinline__ unsigned f2tf(float f) {
    unsigned u;
    asm("cvt.rna.tf32.f32 %0, %1;" : "=r"(u) : "f"(f));
    return u;
}

__device__ __forceinline__ void mma_tf32(float d[4], const unsigned a[4], const unsigned b[2]) {
    asm volatile(
        "mma.sync.aligned.m16n8k8.row.col.f32.tf32.tf32.f32 "
        "{%0,%1,%2,%3}, {%4,%5,%6,%7}, {%8,%9}, {%0,%1,%2,%3};"
        : "+f"(d[0]), "+f"(d[1]), "+f"(d[2]), "+f"(d[3])
        : "r"(a[0]), "r"(a[1]), "r"(a[2]), "r"(a[3]), "r"(b[0]), "r"(b[1]));
}

__device__ __forceinline__ void cp_async16(unsigned saddr, const void* g) {
    asm volatile("cp.async.cg.shared.global [%0], [%1], 16;" :: "r"(saddr), "l"(g));
}

// ---------------- modulation: silu(vec) @ mod_w + mod_b (K-split, 192 blocks) ----------------
__global__ __launch_bounds__(256) void mod_kernel(
    const float* __restrict__ vec,
    const float* __restrict__ ow, const float* __restrict__ ob,
    const float* __restrict__ cw, const float* __restrict__ cb) {
    __shared__ float sv[DM];
    __shared__ float part[256];
    int tid = threadIdx.x;
    for (int i = tid; i < DM; i += 256) {
        float v = vec[i];
        sv[i] = v / (1.0f + expf(-v));
    }
    __syncthreads();
    int j0 = blockIdx.x * 64;                 // 0..12287 step 64
    int stream = j0 / (6 * DM);
    int jbase = j0 % (6 * DM);
    int jl = tid & 63;
    int kc = tid >> 6;                        // 0..3
    int jj = jbase + jl;
    const float* w = stream ? cw : ow;
    const float* wp = w + (size_t)(kc * 256) * (6 * DM) + jj;
    const float* svp = sv + kc * 256;
    float acc = 0.0f;
#pragma unroll 8
    for (int k = 0; k < 256; k++)
        acc += svp[k] * wp[(size_t)k * (6 * DM)];
    part[tid] = acc;
    __syncthreads();
    if (kc == 0) {
        const float* b = stream ? cb : ob;
        float s = part[tid] + part[tid + 64] + part[tid + 128] + part[tid + 192];
        g_mod[stream * 6 * DM + jbase + jl] = s + b[jj];
    }
}

// ---------------- layernorm + modulation, merged obs/cond (shuffle reduce) ----------------
__global__ void ln_mod_kernel(const float* __restrict__ x1, const float* __restrict__ x2,
                              float* __restrict__ y, int shiftc, int scalec) {
    int row = blockIdx.x;
    int tid = threadIdx.x;
    int stream = (row >= LO);
    const float* xr = stream ? (x2 + (size_t)(row - LO) * DM) : (x1 + (size_t)row * DM);
    __shared__ float ws[8], wss[8];
    float s = 0.0f, ss = 0.0f;
    float xv[4];
#pragma unroll
    for (int i = 0; i < 4; i++) {
        float v = xr[tid + i * 256];
        xv[i] = v;
        s += v; ss += v * v;
    }
#pragma unroll
    for (int off = 16; off > 0; off >>= 1) {
        s += __shfl_xor_sync(0xffffffffu, s, off);
        ss += __shfl_xor_sync(0xffffffffu, ss, off);
    }
    if ((tid & 31) == 0) { ws[tid >> 5] = s; wss[tid >> 5] = ss; }
    __syncthreads();
    float S = 0.0f, SS = 0.0f;
#pragma unroll
    for (int i = 0; i < 8; i++) { S += ws[i]; SS += wss[i]; }
    float mean = S * (1.0f / DM);
    float var = SS * (1.0f / DM) - mean * mean;
    float inv = rsqrtf(var + 1e-6f);
    const float* sh = g_mod + (stream * 6 + shiftc) * DM;
    const float* sc = g_mod + (stream * 6 + scalec) * DM;
    float* yr = y + (size_t)row * DM;
#pragma unroll
    for (int i = 0; i < 4; i++) {
        int c = tid + i * 256;
        yr[c] = (xv[i] - mean) * inv * (1.0f + sc[c]) + sh[c];
    }
}

// ---------------- tf32 tensor-core GEMM, merged obs/cond pair ----------------
// BM=128, BN=128, BK=32; 8 warps in 2x4; warp tile 64x32; mma m16n8k8.
// mode 0: C = AB (+bias)    mode 1: C = resid + gate*(AB + bias)
// mode 2: C = gelu_tanh(AB + bias)
__global__ __launch_bounds__(256) void mma_gemm2_kernel(
    const float* __restrict__ A1, const float* __restrict__ B1, float* __restrict__ C1,
    const float* __restrict__ A2, const float* __restrict__ B2, float* __restrict__ C2,
    int M1, int N, int K,
    const float* __restrict__ bias1, const float* __restrict__ bias2,
    const float* __restrict__ resid1, const float* __restrict__ resid2,
    int gidx1, int gidx2, int mode) {
    __shared__ unsigned As[128][36];   // row-major, pad 4
    __shared__ unsigned Bs[32][136];   // k-major,   pad 8

    int tid = threadIdx.x;
    int lane = tid & 31, warp = tid >> 5;
    int wm = warp >> 2, wn = warp & 3;          // 2 x 4 warp grid
    int g = lane >> 2, tg = lane & 3;
    int by = blockIdx.y * 128, col0 = blockIdx.x * 128;

    const float *A, *B, *bias, *resid;
    float* C;
    int gidx, row0;
    if (by < M1) { A = A1; B = B1; C = C1; bias = bias1; resid = resid1; gidx = gidx1; row0 = by; }
    else         { A = A2; B = B2; C = C2; bias = bias2; resid = resid2; gidx = gidx2; row0 = by - M1; }

    float acc[16][4];
#pragma unroll
    for (int i = 0; i < 16; i++)
#pragma unroll
        for (int j = 0; j < 4; j++) acc[i][j] = 0.0f;

    for (int k0 = 0; k0 < K; k0 += 32) {
#pragma unroll
        for (int i = 0; i < 4; i++) {
            int idx = tid + i * 256;
            int r = idx >> 3, c4 = (idx & 7) << 2;
            float4 v = *(const float4*)&A[(size_t)(row0 + r) * K + k0 + c4];
            As[r][c4 + 0] = f2tf(v.x); As[r][c4 + 1] = f2tf(v.y);
            As[r][c4 + 2] = f2tf(v.z); As[r][c4 + 3] = f2tf(v.w);
        }
#pragma unroll
        for (int i = 0; i < 4; i++) {
            int idx = tid + i * 256;
            int r = idx >> 5, c4 = (idx & 31) << 2;
            float4 v = *(const float4*)&B[(size_t)(k0 + r) * N + col0 + c4];
            Bs[r][c4 + 0] = f2tf(v.x); Bs[r][c4 + 1] = f2tf(v.y);
            Bs[r][c4 + 2] = f2tf(v.z); Bs[r][c4 + 3] = f2tf(v.w);
        }
        __syncthreads();
#pragma unroll
        for (int k8 = 0; k8 < 4; k8++) {
            unsigned a[4][4], b[4][2];
#pragma unroll
            for (int mt = 0; mt < 4; mt++) {
                int r = wm * 64 + mt * 16;
                a[mt][0] = As[r + g][k8 * 8 + tg];
                a[mt][1] = As[r + 8 + g][k8 * 8 + tg];
                a[mt][2] = As[r + g][k8 * 8 + tg + 4];
                a[mt][3] = As[r + 8 + g][k8 * 8 + tg + 4];
            }
#pragma unroll
            for (int nt = 0; nt < 4; nt++) {
                int c = wn * 32 + nt * 8 + g;
                b[nt][0] = Bs[k8 * 8 + tg][c];
                b[nt][1] = Bs[k8 * 8 + tg + 4][c];
            }
#pragma unroll
            for (int mt = 0; mt < 4; mt++)
#pragma unroll
                for (int nt = 0; nt < 4; nt++)
                    mma_tf32(acc[mt * 4 + nt], a[mt], b[nt]);
        }
        __syncthreads();
    }

    const float* gate = (gidx >= 0) ? (g_mod + gidx * DM) : nullptr;
#pragma unroll
    for (int mt = 0; mt < 4; mt++) {
#pragma unroll
        for (int nt = 0; nt < 4; nt++) {
            int c = col0 + wn * 32 + nt * 8 + 2 * tg;
#pragma unroll
            for (int half = 0; half < 2; half++) {
                int r = row0 + wm * 64 + mt * 16 + g + half * 8;
#pragma unroll
                for (int jj = 0; jj < 2; jj++) {
                    int cc = c + jj;
                    float v = acc[mt * 4 + nt][half * 2 + jj];
                    if (bias) v += bias[cc];
                    if (mode == 1) {
                        v = resid[(size_t)r * N + cc] + gate[cc] * v;
                    } else if (mode == 2) {
                        float t = v;
                        v = 0.5f * t * (1.0f + tanhf(0.7978845608f * (t + 0.044715f * t * t * t)));
                    }
                    C[(size_t)r * N + cc] = v;
                }
            }
        }
    }
}

// ---------------- qkv post: rmsnorm(q,k) + rope, scatter tf32 words to [h][l][dh] ----------------
__global__ void qkv_post_kernel(const float* __restrict__ pe,
                                const float* __restrict__ oqs, const float* __restrict__ oks,
                                const float* __restrict__ cqs, const float* __restrict__ cks) {
    int gl = blockIdx.x;      // global token (cond first)
    int h = blockIdx.y;
    int d = threadIdx.x;      // 0..63
    bool is_cond = gl < LC;
    const float* src = is_cond ? (g_qkv + (size_t)LO * 3 * DM + (size_t)gl * 3 * DM)
                               : (g_qkv + (size_t)(gl - LC) * 3 * DM);
    const float* qs = is_cond ? cqs : oqs;
    const float* ks = is_cond ? cks : oks;
    float qv = src[h * DH + d];
    float kv = src[DM + h * DH + d];
    float vv = src[2 * DM + h * DH + d];
    float qss = qv * qv, kss = kv * kv;
#pragma unroll
    for (int off = 16; off > 0; off >>= 1) {
        qss += __shfl_xor_sync(0xffffffffu, qss, off);
        kss += __shfl_xor_sync(0xffffffffu, kss, off);
    }
    __shared__ float red[4];
    int w = d >> 5;
    if ((d & 31) == 0) { red[w] = qss; red[2 + w] = kss; }
    __syncthreads();
    qss = red[0] + red[1];
    kss = red[2] + red[3];
    float qn = qv * rsqrtf(qss * (1.0f / DH) + 1e-6f) * qs[d];
    float kn = kv * rsqrtf(kss * (1.0f / DH) + 1e-6f) * ks[d];
    __shared__ float sq[DH], sk[DH];
    sq[d] = qn; sk[d] = kn;
    __syncthreads();
    int p = d >> 1, j = d & 1;
    const float* pp = pe + (((size_t)gl * 32 + p) * 2 + j) * 2;
    float q0 = sq[2 * p], q1 = sq[2 * p + 1];
    float k0 = sk[2 * p], k1 = sk[2 * p + 1];
    float qo = pp[0] * q0 + pp[1] * q1;
    float ko = pp[0] * k0 + pp[1] * k1;
    size_t oidx = ((size_t)h * LT + gl) * DH + d;
    g_q[oidx] = f2tf(qo * 0.125f);   // pre-scale by 1/sqrt(64), pre-convert to tf32
    g_k[oidx] = f2tf(ko);
    g_v[oidx] = f2tf(vv);
}

// ---------------- attention: flash w/ tf32 mma + cp.async pipelined K/V ----------------
// 8 warps in 4x2 (wm: 32 q-rows each, wn: 32 cols each). mma m16n8k8.
#define AS 68   // padded row stride (u32 words)
__global__ __launch_bounds__(256, 2) void attn_mma_kernel() {
    extern __shared__ unsigned smu[];
    unsigned* Qs = smu;                    // [128][AS] tf32
    unsigned* Ks = Qs + 128 * AS;          // [64][AS]  tf32
    unsigned* Vs = Ks + 64 * AS;           // [64][AS]  tf32
    float* Ps = (float*)(Vs + 64 * AS);    // [128][AS] scores: fp32 then tf32 words
    float* row_m = Ps + 128 * AS;          // [128]
    float* row_l = row_m + 128;            // [128]
    float* corr_s = row_l + 128;           // [128]
    unsigned* Psu = (unsigned*)Ps;

    int h = blockIdx.x;
    int q0 = blockIdx.y * 128;
    int tid = threadIdx.x;
    int lane = tid & 31, warp = tid >> 5;
    int wm = warp >> 1, wn = warp & 1;     // 4 x 2
    int g = lane >> 2, tg = lane & 3;

    const unsigned* qb = g_q + ((size_t)h * LT + q0) * DH;
    const unsigned* kb = g_k + (size_t)h * LT * DH;
    const unsigned* vb = g_v + (size_t)h * LT * DH;

    unsigned ks_sm = (unsigned)__cvta_generic_to_shared(Ks);
    unsigned vs_sm = (unsigned)__cvta_generic_to_shared(Vs);
    int ld_r = tid >> 4, ld_c = (tid & 15) << 2;   // thread's 4-chunk pattern base

    // load Q tile: 128 rows x 64 words = 2048 uint4 slots
#pragma unroll
    for (int i = 0; i < 8; i++) {
        int idx = tid + i * 256;
        int r = idx >> 4, c = (idx & 15) << 2;
        *(uint4*)&Qs[r * AS + c] = *(const uint4*)&qb[(size_t)r * DH + c];
    }
    if (tid < 128) { row_m[tid] = -3e38f; row_l[tid] = 0.0f; }

    // prologue: async K0, V0 (separate commit groups; K then V)
#pragma unroll
    for (int i = 0; i < 4; i++) {
        int r = ld_r + i * 16;
        cp_async16(ks_sm + (r * AS + ld_c) * 4, &kb[(size_t)r * DH + ld_c]);
    }
    asm volatile("cp.async.commit_group;" ::: "memory");
#pragma unroll
    for (int i = 0; i < 4; i++) {
        int r = ld_r + i * 16;
        cp_async16(vs_sm + (r * AS + ld_c) * 4, &vb[(size_t)r * DH + ld_c]);
    }
    asm volatile("cp.async.commit_group;" ::: "memory");

    float acc_o[2][4][4];
#pragma unroll
    for (int mt = 0; mt < 2; mt++)
#pragma unroll
        for (int nt = 0; nt < 4; nt++)
#pragma unroll
            for (int j = 0; j < 4; j++) acc_o[mt][nt][j] = 0.0f;

    for (int kt = 0; kt < LT; kt += 64) {
        int ktn = (kt + 64 < LT) ? kt + 64 : 0;    // next tile (clamped; last-iter loads are dead)

        asm volatile("cp.async.wait_group 1;" ::: "memory");   // K(t) done (V(t) may pend)
        __syncthreads();                                        // K visible; prior PV reads of Ps done

        // ---- S = Q K^T : warp computes 32x32 ----
        float acc_s[2][4][4];
#pragma unroll
        for (int mt = 0; mt < 2; mt++)
#pragma unroll
            for (int nt = 0; nt < 4; nt++)
#pragma unroll
                for (int j = 0; j < 4; j++) acc_s[mt][nt][j] = 0.0f;
#pragma unroll
        for (int k8 = 0; k8 < 8; k8++) {
            unsigned a[2][4], b[4][2];
#pragma unroll
            for (int mt = 0; mt < 2; mt++) {
                int r = wm * 32 + mt * 16;
                a[mt][0] = Qs[(r + g) * AS + k8 * 8 + tg];
                a[mt][1] = Qs[(r + 8 + g) * AS + k8 * 8 + tg];
                a[mt][2] = Qs[(r + g) * AS + k8 * 8 + tg + 4];
                a[mt][3] = Qs[(r + 8 + g) * AS + k8 * 8 + tg + 4];
            }
#pragma unroll
            for (int nt = 0; nt < 4; nt++) {
                int c = wn * 32 + nt * 8 + g;
                b[nt][0] = Ks[c * AS + k8 * 8 + tg];
                b[nt][1] = Ks[c * AS + k8 * 8 + tg + 4];
            }
#pragma unroll
            for (int mt = 0; mt < 2; mt++)
#pragma unroll
                for (int nt = 0; nt < 4; nt++)
                    mma_tf32(acc_s[mt][nt], a[mt], b[nt]);
        }
        // scatter S -> Ps (fp32)
#pragma unroll
        for (int mt = 0; mt < 2; mt++)
#pragma unroll
            for (int nt = 0; nt < 4; nt++)
#pragma unroll
                for (int half = 0; half < 2; half++) {
                    int r = wm * 32 + mt * 16 + half * 8 + g;
                    int c = wn * 32 + nt * 8 + 2 * tg;
                    Ps[r * AS + c]     = acc_s[mt][nt][half * 2 + 0];
                    Ps[r * AS + c + 1] = acc_s[mt][nt][half * 2 + 1];
                }
        __syncthreads();                            // Ks free, Ps complete

        // issue K(t+1) into Ks (overlaps softmax + PV)
#pragma unroll
        for (int i = 0; i < 4; i++) {
            int r = ld_r + i * 16;
            cp_async16(ks_sm + (r * AS + ld_c) * 4, &kb[(size_t)(ktn + r) * DH + ld_c]);
        }
        asm volatile("cp.async.commit_group;" ::: "memory");

        // ---- online softmax: 2 threads per row, 32 cols each; store P as tf32 ----
        {
            int r = tid >> 1, halfc = tid & 1;
            float* prow = &Ps[r * AS + halfc * 32];
            unsigned* prow_u = (unsigned*)prow;
            float mx = -3e38f;
#pragma unroll
            for (int c = 0; c < 32; c++) mx = fmaxf(mx, prow[c]);
            mx = fmaxf(mx, __shfl_xor_sync(0xffffffffu, mx, 1));
            float m_old = row_m[r];
            float m_new = fmaxf(m_old, mx);
            float corr = __expf(m_old - m_new);
            float ls = 0.0f;
#pragma unroll
            for (int c = 0; c < 32; c++) {
                float p = __expf(prow[c] - m_new);
                prow_u[c] = f2tf(p);
                ls += p;
            }
            ls += __shfl_xor_sync(0xffffffffu, ls, 1);
            if (halfc == 0) {
                row_m[r] = m_new;
                row_l[r] = row_l[r] * corr + ls;
                corr_s[r] = corr;
            }
        }
        asm volatile("cp.async.wait_group 1;" ::: "memory");   // V(t) done (K(t+1) pends)
        __syncthreads();                                        // V + softmax results visible

        // ---- rescale O, then O += P V ----
#pragma unroll
        for (int mt = 0; mt < 2; mt++)
#pragma unroll
            for (int half = 0; half < 2; half++) {
                float cr = corr_s[wm * 32 + mt * 16 + half * 8 + g];
#pragma unroll
                for (int nt = 0; nt < 4; nt++) {
                    acc_o[mt][nt][half * 2 + 0] *= cr;
                    acc_o[mt][nt][half * 2 + 1] *= cr;
                }
            }
#pragma unroll
        for (int k8 = 0; k8 < 8; k8++) {
            unsigned a[2][4], b[4][2];
#pragma unroll
            for (int mt = 0; mt < 2; mt++) {
                int r = wm * 32 + mt * 16;
                a[mt][0] = Psu[(r + g) * AS + k8 * 8 + tg];
                a[mt][1] = Psu[(r + 8 + g) * AS + k8 * 8 + tg];
                a[mt][2] = Psu[(r + g) * AS + k8 * 8 + tg + 4];
                a[mt][3] = Psu[(r + 8 + g) * AS + k8 * 8 + tg + 4];
            }
#pragma unroll
            for (int nt = 0; nt < 4; nt++) {
                int c = wn * 32 + nt * 8 + g;          // output col (d)
                b[nt][0] = Vs[(k8 * 8 + tg) * AS + c];
                b[nt][1] = Vs[(k8 * 8 + tg + 4) * AS + c];
            }
#pragma unroll
            for (int mt = 0; mt < 2; mt++)
#pragma unroll
                for (int nt = 0; nt < 4; nt++)
                    mma_tf32(acc_o[mt][nt], a[mt], b[nt]);
        }
        __syncthreads();                            // Vs reads done

        // issue V(t+1) into Vs (overlaps next tile's S-mma + softmax)
#pragma unroll
        for (int i = 0; i < 4; i++) {
            int r = ld_r + i * 16;
            cp_async16(vs_sm + (r * AS + ld_c) * 4, &vb[(size_t)(ktn + r) * DH + ld_c]);
        }
        asm volatile("cp.async.commit_group;" ::: "memory");
    }
    asm volatile("cp.async.wait_group 0;" ::: "memory");
    __syncthreads();

    // epilogue: normalize by row_l, write out
#pragma unroll
    for (int mt = 0; mt < 2; mt++)
#pragma unroll
        for (int half = 0; half < 2; half++) {
            int r = wm * 32 + mt * 16 + half * 8 + g;
            float inv = 1.0f / row_l[r];
#pragma unroll
            for (int nt = 0; nt < 4; nt++) {
                int c = wn * 32 + nt * 8 + 2 * tg;
                float* dst = &g_attn[(size_t)(q0 + r) * DM + h * DH + c];
                dst[0] = acc_o[mt][nt][half * 2 + 0] * inv;
                dst[1] = acc_o[mt][nt][half * 2 + 1] * inv;
            }
        }
}

// ---------------- launch ----------------
extern "C" void kernel_launch(void* const* d_in, const int* in_sizes, int n_in,
                              void* d_out, int out_size) {
    const float* obs   = (const float*)d_in[0];
    const float* cond  = (const float*)d_in[1];
    const float* vec   = (const float*)d_in[2];
    const float* pe    = (const float*)d_in[3];
    const float* o_mod_w = (const float*)d_in[4];
    const float* o_mod_b = (const float*)d_in[5];
    const float* o_qkv_w = (const float*)d_in[6];
    const float* o_q_s   = (const float*)d_in[7];
    const float* o_k_s   = (const float*)d_in[8];
    const float* o_proj_w = (const float*)d_in[9];
    const float* o_proj_b = (const float*)d_in[10];
    const float* o_mlp_w1 = (const float*)d_in[11];
    const float* o_mlp_b1 = (const float*)d_in[12];
    const float* o_mlp_w2 = (const float*)d_in[13];
    const float* o_mlp_b2 = (const float*)d_in[14];
    const float* c_mod_w = (const float*)d_in[15];
    const float* c_mod_b = (const float*)d_in[16];
    const float* c_qkv_w = (const float*)d_in[17];
    const float* c_q_s   = (const float*)d_in[18];
    const float* c_k_s   = (const float*)d_in[19];
    const float* c_proj_w = (const float*)d_in[20];
    const float* c_proj_b = (const float*)d_in[21];
    const float* c_mlp_w1 = (const float*)d_in[22];
    const float* c_mlp_b1 = (const float*)d_in[23];
    const float* c_mlp_w2 = (const float*)d_in[24];
    const float* c_mlp_b2 = (const float*)d_in[25];

    float* out = (float*)d_out;
    float* out_obs = out;                 // rows 0..LO-1
    float* out_cond = out + (size_t)LO * DM;

    float *p_xm, *p_qkv, *p_attn, *p_h;
    cudaGetSymbolAddress((void**)&p_xm, g_xm);
    cudaGetSymbolAddress((void**)&p_qkv, g_qkv);
    cudaGetSymbolAddress((void**)&p_attn, g_attn);
    cudaGetSymbolAddress((void**)&p_h, g_h);

    int smem_bytes = (int)((384 * AS) * 4 + 3 * 128 * 4);
    static int init = 0;
    if (!init) {
        init = 1;
        cudaFuncSetAttribute(attn_mma_kernel, cudaFuncAttributeMaxDynamicSharedMemorySize, smem_bytes);
    }

    // 1. modulation vectors (K-split for parallelism)
    mod_kernel<<<192, 256>>>(vec, o_mod_w, o_mod_b, c_mod_w, c_mod_b);

    // 2. LN + mod (chunks: 0=shift1, 1=scale1), merged
    ln_mod_kernel<<<LT, 256>>>(obs, cond, p_xm, 0, 1);

    // 3. qkv GEMMs, merged
    {
        dim3 g(3 * DM / 128, LT / 128);
        mma_gemm2_kernel<<<g, 256>>>(p_xm, o_qkv_w, p_qkv,
                                     p_xm + (size_t)LO * DM, c_qkv_w, p_qkv + (size_t)LO * 3 * DM,
                                     LO, 3 * DM, DM,
                                     nullptr, nullptr, nullptr, nullptr, -1, -1, 0);
    }

    // 4. rmsnorm + rope + scatter (tf32 pre-converted)
    {
        dim3 g(LT, NH);
        qkv_post_kernel<<<g, 64>>>(pe, o_q_s, o_k_s, c_q_s, c_k_s);
    }

    // 5. attention (tensor-core flash, cp.async pipelined)
    {
        dim3 g(NH, LT / 128);
        attn_mma_kernel<<<g, 256, smem_bytes>>>();
    }

    // 6. proj + gated residual (gate1 = chunk 2), merged
    {
        dim3 g(DM / 128, LT / 128);
        mma_gemm2_kernel<<<g, 256>>>(p_attn + (size_t)LC * DM, o_proj_w, out_obs,
                                     p_attn, c_proj_w, out_cond,
                                     LO, DM, DM,
                                     o_proj_b, c_proj_b, obs, cond, 0 * 6 + 2, 1 * 6 + 2, 1);
    }

    // 7. LN2 + mod (chunks: 3=shift2, 4=scale2), merged
    ln_mod_kernel<<<LT, 256>>>(out_obs, out_cond, p_xm, 3, 4);

    // 8. mlp1 + gelu, merged
    {
        dim3 g(MH / 128, LT / 128);
        mma_gemm2_kernel<<<g, 256>>>(p_xm, o_mlp_w1, p_h,
                                     p_xm + (size_t)LO * DM, c_mlp_w1, p_h + (size_t)LO * MH,
                                     LO, MH, DM,
                                     o_mlp_b1, c_mlp_b1, nullptr, nullptr, -1, -1, 2);
    }

    // 9. mlp2 + gated residual (gate2 = chunk 5), merged, in-place residual on d_out
    {
        dim3 g(DM / 128, LT / 128);
        mma_gemm2_kernel<<<g, 256>>>(p_h, o_mlp_w2, out_obs,
                                     p_h + (size_t)LO * MH, c_mlp_w2, out_cond,
                                     LO, DM, MH,
                                     o_mlp_b2, c_mlp_b2, out_obs, out_cond, 0 * 6 + 5, 1 * 6 + 5, 1);
    }
}

// round 13
// speedup vs baseline: 1.3987x; 1.0833x over previous
#include <cuda_runtime.h>
#include <cuda_bf16.h>
#include <math.h>

#define LO 3072
#define LC 1024
#define LT 4096   // LO + LC
#define DM 1024   // model dim
#define NH 16
#define DH 64
#define MH 4096

// ---------------- scratch (device globals; no allocation allowed) ----------------
__device__ float g_mod[12 * DM];          // [2 streams][6 chunks][1024]
__device__ float g_xm[LT * DM];           // modulated LN output (obs rows 0..LO-1, cond at LO)
__device__ float g_qkv[LT * 3 * DM];      // raw qkv (obs rows at 0, cond rows at LO*3*DM)
__device__ unsigned g_q[NH * LT * DH];    // [h][l][dh] tf32 words, q pre-scaled by 0.125*log2e
__device__ unsigned g_k[NH * LT * DH];    // tf32 words
__device__ unsigned g_v[NH * LT * DH];    // tf32 words
__device__ float g_attn[LT * DM];         // attention out fp32, global l order
__device__ float g_h[LT * MH];            // mlp hidden

// ---------------- helpers ----------------
__device__ __forceinline__ unsigned f2tf(float f) {
    unsigned u;
    asm("cvt.rna.tf32.f32 %0, %1;" : "=r"(u) : "f"(f));
    return u;
}

__device__ __forceinline__ float fexp2(float x) {
    float y;
    asm("ex2.approx.ftz.f32 %0, %1;" : "=f"(y) : "f"(x));
    return y;
}

__device__ __forceinline__ void mma_tf32(float d[4], const unsigned a[4], const unsigned b[2]) {
    asm volatile(
        "mma.sync.aligned.m16n8k8.row.col.f32.tf32.tf32.f32 "
        "{%0,%1,%2,%3}, {%4,%5,%6,%7}, {%8,%9}, {%0,%1,%2,%3};"
        : "+f"(d[0]), "+f"(d[1]), "+f"(d[2]), "+f"(d[3])
        : "r"(a[0]), "r"(a[1]), "r"(a[2]), "r"(a[3]), "r"(b[0]), "r"(b[1]));
}

__device__ __forceinline__ void cp_async16(unsigned saddr, const void* g) {
    asm volatile("cp.async.cg.shared.global [%0], [%1], 16;" :: "r"(saddr), "l"(g));
}

// ---------------- modulation: silu(vec) @ mod_w + mod_b (K-split, 192 blocks) ----------------
__global__ __launch_bounds__(256) void mod_kernel(
    const float* __restrict__ vec,
    const float* __restrict__ ow, const float* __restrict__ ob,
    const float* __restrict__ cw, const float* __restrict__ cb) {
    __shared__ float sv[DM];
    __shared__ float part[256];
    int tid = threadIdx.x;
    for (int i = tid; i < DM; i += 256) {
        float v = vec[i];
        sv[i] = v / (1.0f + expf(-v));
    }
    __syncthreads();
    int j0 = blockIdx.x * 64;                 // 0..12287 step 64
    int stream = j0 / (6 * DM);
    int jbase = j0 % (6 * DM);
    int jl = tid & 63;
    int kc = tid >> 6;                        // 0..3
    int jj = jbase + jl;
    const float* w = stream ? cw : ow;
    const float* wp = w + (size_t)(kc * 256) * (6 * DM) + jj;
    const float* svp = sv + kc * 256;
    float acc = 0.0f;
#pragma unroll 8
    for (int k = 0; k < 256; k++)
        acc += svp[k] * wp[(size_t)k * (6 * DM)];
    part[tid] = acc;
    __syncthreads();
    if (kc == 0) {
        const float* b = stream ? cb : ob;
        float s = part[tid] + part[tid + 64] + part[tid + 128] + part[tid + 192];
        g_mod[stream * 6 * DM + jbase + jl] = s + b[jj];
    }
}

// ---------------- layernorm + modulation, merged obs/cond (shuffle reduce) ----------------
__global__ void ln_mod_kernel(const float* __restrict__ x1, const float* __restrict__ x2,
                              float* __restrict__ y, int shiftc, int scalec) {
    int row = blockIdx.x;
    int tid = threadIdx.x;
    int stream = (row >= LO);
    const float* xr = stream ? (x2 + (size_t)(row - LO) * DM) : (x1 + (size_t)row * DM);
    __shared__ float ws[8], wss[8];
    float s = 0.0f, ss = 0.0f;
    float xv[4];
#pragma unroll
    for (int i = 0; i < 4; i++) {
        float v = xr[tid + i * 256];
        xv[i] = v;
        s += v; ss += v * v;
    }
#pragma unroll
    for (int off = 16; off > 0; off >>= 1) {
        s += __shfl_xor_sync(0xffffffffu, s, off);
        ss += __shfl_xor_sync(0xffffffffu, ss, off);
    }
    if ((tid & 31) == 0) { ws[tid >> 5] = s; wss[tid >> 5] = ss; }
    __syncthreads();
    float S = 0.0f, SS = 0.0f;
#pragma unroll
    for (int i = 0; i < 8; i++) { S += ws[i]; SS += wss[i]; }
    float mean = S * (1.0f / DM);
    float var = SS * (1.0f / DM) - mean * mean;
    float inv = rsqrtf(var + 1e-6f);
    const float* sh = g_mod + (stream * 6 + shiftc) * DM;
    const float* sc = g_mod + (stream * 6 + scalec) * DM;
    float* yr = y + (size_t)row * DM;
#pragma unroll
    for (int i = 0; i < 4; i++) {
        int c = tid + i * 256;
        yr[c] = (xv[i] - mean) * inv * (1.0f + sc[c]) + sh[c];
    }
}

// ---------------- tf32 tensor-core GEMM, merged obs/cond pair ----------------
// BM=128, BN=128, BK=32; 8 warps in 2x4; warp tile 64x32; mma m16n8k8.
// mode 0: C = AB (+bias)    mode 1: C = resid + gate*(AB + bias)
// mode 2: C = gelu_tanh(AB + bias)
__global__ __launch_bounds__(256) void mma_gemm2_kernel(
    const float* __restrict__ A1, const float* __restrict__ B1, float* __restrict__ C1,
    const float* __restrict__ A2, const float* __restrict__ B2, float* __restrict__ C2,
    int M1, int N, int K,
    const float* __restrict__ bias1, const float* __restrict__ bias2,
    const float* __restrict__ resid1, const float* __restrict__ resid2,
    int gidx1, int gidx2, int mode) {
    __shared__ unsigned As[128][36];   // row-major, pad 4
    __shared__ unsigned Bs[32][136];   // k-major,   pad 8

    int tid = threadIdx.x;
    int lane = tid & 31, warp = tid >> 5;
    int wm = warp >> 2, wn = warp & 3;          // 2 x 4 warp grid
    int g = lane >> 2, tg = lane & 3;
    int by = blockIdx.y * 128, col0 = blockIdx.x * 128;

    const float *A, *B, *bias, *resid;
    float* C;
    int gidx, row0;
    if (by < M1) { A = A1; B = B1; C = C1; bias = bias1; resid = resid1; gidx = gidx1; row0 = by; }
    else         { A = A2; B = B2; C = C2; bias = bias2; resid = resid2; gidx = gidx2; row0 = by - M1; }

    float acc[16][4];
#pragma unroll
    for (int i = 0; i < 16; i++)
#pragma unroll
        for (int j = 0; j < 4; j++) acc[i][j] = 0.0f;

    for (int k0 = 0; k0 < K; k0 += 32) {
#pragma unroll
        for (int i = 0; i < 4; i++) {
            int idx = tid + i * 256;
            int r = idx >> 3, c4 = (idx & 7) << 2;
            float4 v = *(const float4*)&A[(size_t)(row0 + r) * K + k0 + c4];
            As[r][c4 + 0] = f2tf(v.x); As[r][c4 + 1] = f2tf(v.y);
            As[r][c4 + 2] = f2tf(v.z); As[r][c4 + 3] = f2tf(v.w);
        }
#pragma unroll
        for (int i = 0; i < 4; i++) {
            int idx = tid + i * 256;
            int r = idx >> 5, c4 = (idx & 31) << 2;
            float4 v = *(const float4*)&B[(size_t)(k0 + r) * N + col0 + c4];
            Bs[r][c4 + 0] = f2tf(v.x); Bs[r][c4 + 1] = f2tf(v.y);
            Bs[r][c4 + 2] = f2tf(v.z); Bs[r][c4 + 3] = f2tf(v.w);
        }
        __syncthreads();
#pragma unroll
        for (int k8 = 0; k8 < 4; k8++) {
            unsigned a[4][4], b[4][2];
#pragma unroll
            for (int mt = 0; mt < 4; mt++) {
                int r = wm * 64 + mt * 16;
                a[mt][0] = As[r + g][k8 * 8 + tg];
                a[mt][1] = As[r + 8 + g][k8 * 8 + tg];
                a[mt][2] = As[r + g][k8 * 8 + tg + 4];
                a[mt][3] = As[r + 8 + g][k8 * 8 + tg + 4];
            }
#pragma unroll
            for (int nt = 0; nt < 4; nt++) {
                int c = wn * 32 + nt * 8 + g;
                b[nt][0] = Bs[k8 * 8 + tg][c];
                b[nt][1] = Bs[k8 * 8 + tg + 4][c];
            }
#pragma unroll
            for (int mt = 0; mt < 4; mt++)
#pragma unroll
                for (int nt = 0; nt < 4; nt++)
                    mma_tf32(acc[mt * 4 + nt], a[mt], b[nt]);
        }
        __syncthreads();
    }

    const float* gate = (gidx >= 0) ? (g_mod + gidx * DM) : nullptr;
#pragma unroll
    for (int mt = 0; mt < 4; mt++) {
#pragma unroll
        for (int nt = 0; nt < 4; nt++) {
            int c = col0 + wn * 32 + nt * 8 + 2 * tg;
#pragma unroll
            for (int half = 0; half < 2; half++) {
                int r = row0 + wm * 64 + mt * 16 + g + half * 8;
#pragma unroll
                for (int jj = 0; jj < 2; jj++) {
                    int cc = c + jj;
                    float v = acc[mt * 4 + nt][half * 2 + jj];
                    if (bias) v += bias[cc];
                    if (mode == 1) {
                        v = resid[(size_t)r * N + cc] + gate[cc] * v;
                    } else if (mode == 2) {
                        float t = v;
                        v = 0.5f * t * (1.0f + tanhf(0.7978845608f * (t + 0.044715f * t * t * t)));
                    }
                    C[(size_t)r * N + cc] = v;
                }
            }
        }
    }
}

// ---------------- qkv post: 1 warp per (token, head); shuffle rmsnorm, paired rope ----------------
// block (32, 8): warp y handles heads y*2 + {0,1} for token gl. Lane holds dh pair (2*lane, 2*lane+1).
__global__ __launch_bounds__(256) void qkv_post_kernel(const float* __restrict__ pe,
                                const float* __restrict__ oqs, const float* __restrict__ oks,
                                const float* __restrict__ cqs, const float* __restrict__ cks) {
    int gl = blockIdx.x;      // global token (cond first)
    int lane = threadIdx.x;   // 0..31
    int y = threadIdx.y;      // 0..7
    bool is_cond = gl < LC;
    const float* src = is_cond ? (g_qkv + (size_t)LO * 3 * DM + (size_t)gl * 3 * DM)
                               : (g_qkv + (size_t)(gl - LC) * 3 * DM);
    const float* qs = is_cond ? cqs : oqs;
    const float* ks = is_cond ? cks : oks;
    // pe pair coefficients for p = lane: (j0i0, j0i1, j1i0, j1i1)
    float4 pp = *(const float4*)&pe[(size_t)gl * 128 + lane * 4];
    float qs0 = qs[2 * lane], qs1 = qs[2 * lane + 1];
    float ks0 = ks[2 * lane], ks1 = ks[2 * lane + 1];
#pragma unroll
    for (int hh = 0; hh < 2; hh++) {
        int h = y * 2 + hh;
        float2 q2 = *(const float2*)&src[h * DH + 2 * lane];
        float2 k2 = *(const float2*)&src[DM + h * DH + 2 * lane];
        float2 v2 = *(const float2*)&src[2 * DM + h * DH + 2 * lane];
        float qss = q2.x * q2.x + q2.y * q2.y;
        float kss = k2.x * k2.x + k2.y * k2.y;
#pragma unroll
        for (int off = 16; off > 0; off >>= 1) {
            qss += __shfl_xor_sync(0xffffffffu, qss, off);
            kss += __shfl_xor_sync(0xffffffffu, kss, off);
        }
        float qinv = rsqrtf(qss * (1.0f / DH) + 1e-6f);
        float kinv = rsqrtf(kss * (1.0f / DH) + 1e-6f);
        float qn0 = q2.x * qinv * qs0, qn1 = q2.y * qinv * qs1;
        float kn0 = k2.x * kinv * ks0, kn1 = k2.y * kinv * ks1;
        // rope: out[2p+j] = pe[p][j][0]*x[2p] + pe[p][j][1]*x[2p+1]
        float qo0 = pp.x * qn0 + pp.y * qn1;
        float qo1 = pp.z * qn0 + pp.w * qn1;
        float ko0 = pp.x * kn0 + pp.y * kn1;
        float ko1 = pp.z * kn0 + pp.w * kn1;
        size_t oidx = ((size_t)h * LT + gl) * DH + 2 * lane;
        // q pre-scaled by 0.125 * log2(e) so softmax can use raw ex2
        *(uint2*)&g_q[oidx] = make_uint2(f2tf(qo0 * 0.18033688f), f2tf(qo1 * 0.18033688f));
        *(uint2*)&g_k[oidx] = make_uint2(f2tf(ko0), f2tf(ko1));
        *(uint2*)&g_v[oidx] = make_uint2(f2tf(v2.x), f2tf(v2.y));
    }
}

// ---------------- attention: flash w/ tf32 mma, in-register softmax, cp.async K/V pipeline ----------------
// 8 warps in 4x2 (wm: 32 q-rows each, wn: 32 cols each). mma m16n8k8. Scores in log2 domain.
#define AS 68   // padded row stride (u32 words)
__global__ __launch_bounds__(256, 2) void attn_mma_kernel() {
    extern __shared__ unsigned smu[];
    unsigned* Qs = smu;                    // [128][AS] tf32
    unsigned* Ks = Qs + 128 * AS;          // [64][AS]  tf32
    unsigned* Vs = Ks + 64 * AS;           // [64][AS]  tf32
    unsigned* Psu = Vs + 64 * AS;          // [128][AS] tf32 probabilities
    float* row_m = (float*)(Psu + 128 * AS);   // [128]
    float* row_l = row_m + 128;                // [128]
    float* wmax = row_l + 128;                 // [2][128] per-warp row max
    float* wsum = wmax + 256;                  // [2][128] per-warp row sum

    int h = blockIdx.x;
    int q0 = blockIdx.y * 128;
    int tid = threadIdx.x;
    int lane = tid & 31, warp = tid >> 5;
    int wm = warp >> 1, wn = warp & 1;     // 4 x 2
    int g = lane >> 2, tg = lane & 3;

    const unsigned* qb = g_q + ((size_t)h * LT + q0) * DH;
    const unsigned* kb = g_k + (size_t)h * LT * DH;
    const unsigned* vb = g_v + (size_t)h * LT * DH;

    unsigned ks_sm = (unsigned)__cvta_generic_to_shared(Ks);
    unsigned vs_sm = (unsigned)__cvta_generic_to_shared(Vs);
    int ld_r = tid >> 4, ld_c = (tid & 15) << 2;

    // load Q tile: 128 rows x 64 words = 2048 uint4 slots
#pragma unroll
    for (int i = 0; i < 8; i++) {
        int idx = tid + i * 256;
        int r = idx >> 4, c = (idx & 15) << 2;
        *(uint4*)&Qs[r * AS + c] = *(const uint4*)&qb[(size_t)r * DH + c];
    }
    if (tid < 128) { row_m[tid] = -3e38f; row_l[tid] = 0.0f; }

    // prologue: async K0, V0 (separate commit groups)
#pragma unroll
    for (int i = 0; i < 4; i++) {
        int r = ld_r + i * 16;
        cp_async16(ks_sm + (r * AS + ld_c) * 4, &kb[(size_t)r * DH + ld_c]);
    }
    asm volatile("cp.async.commit_group;" ::: "memory");
#pragma unroll
    for (int i = 0; i < 4; i++) {
        int r = ld_r + i * 16;
        cp_async16(vs_sm + (r * AS + ld_c) * 4, &vb[(size_t)r * DH + ld_c]);
    }
    asm volatile("cp.async.commit_group;" ::: "memory");

    float acc_o[2][4][4];
#pragma unroll
    for (int mt = 0; mt < 2; mt++)
#pragma unroll
        for (int nt = 0; nt < 4; nt++)
#pragma unroll
            for (int j = 0; j < 4; j++) acc_o[mt][nt][j] = 0.0f;

    for (int kt = 0; kt < LT; kt += 64) {
        int ktn = (kt + 64 < LT) ? kt + 64 : 0;

        asm volatile("cp.async.wait_group 1;" ::: "memory");   // K(t) done
        __syncthreads();                                        // [top] K visible; Psu free

        // ---- S = Q K^T (log2 domain; q pre-scaled) ----
        float acc_s[2][4][4];
#pragma unroll
        for (int mt = 0; mt < 2; mt++)
#pragma unroll
            for (int nt = 0; nt < 4; nt++)
#pragma unroll
                for (int j = 0; j < 4; j++) acc_s[mt][nt][j] = 0.0f;
#pragma unroll
        for (int k8 = 0; k8 < 8; k8++) {
            unsigned a[2][4], b[4][2];
#pragma unroll
            for (int mt = 0; mt < 2; mt++) {
                int r = wm * 32 + mt * 16;
                a[mt][0] = Qs[(r + g) * AS + k8 * 8 + tg];
                a[mt][1] = Qs[(r + 8 + g) * AS + k8 * 8 + tg];
                a[mt][2] = Qs[(r + g) * AS + k8 * 8 + tg + 4];
                a[mt][3] = Qs[(r + 8 + g) * AS + k8 * 8 + tg + 4];
            }
#pragma unroll
            for (int nt = 0; nt < 4; nt++) {
                int c = wn * 32 + nt * 8 + g;
                b[nt][0] = Ks[c * AS + k8 * 8 + tg];
                b[nt][1] = Ks[c * AS + k8 * 8 + tg + 4];
            }
#pragma unroll
            for (int mt = 0; mt < 2; mt++)
#pragma unroll
                for (int nt = 0; nt < 4; nt++)
                    mma_tf32(acc_s[mt][nt], a[mt], b[nt]);
        }

        // ---- per-warp row max via shuffles over tg lanes ----
#pragma unroll
        for (int mt = 0; mt < 2; mt++)
#pragma unroll
            for (int half = 0; half < 2; half++) {
                float m = acc_s[mt][0][half * 2];
#pragma unroll
                for (int nt = 0; nt < 4; nt++) {
                    m = fmaxf(m, acc_s[mt][nt][half * 2 + 0]);
                    m = fmaxf(m, acc_s[mt][nt][half * 2 + 1]);
                }
                m = fmaxf(m, __shfl_xor_sync(0xffffffffu, m, 1));
                m = fmaxf(m, __shfl_xor_sync(0xffffffffu, m, 2));
                if (tg == 0) wmax[wn * 128 + wm * 32 + mt * 16 + half * 8 + g] = m;
            }
        __syncthreads();                                        // [A] wmax ready; Ks free

        // issue K(t+1) (overlaps softmax + PV)
#pragma unroll
        for (int i = 0; i < 4; i++) {
            int r = ld_r + i * 16;
            cp_async16(ks_sm + (r * AS + ld_c) * 4, &kb[(size_t)(ktn + r) * DH + ld_c]);
        }
        asm volatile("cp.async.commit_group;" ::: "memory");

        // ---- in-register softmax: exp2, P -> tf32 smem, row sums via shuffles ----
        float mnew[2][2], corr[2][2];
#pragma unroll
        for (int mt = 0; mt < 2; mt++)
#pragma unroll
            for (int half = 0; half < 2; half++) {
                int r = wm * 32 + mt * 16 + half * 8 + g;
                float mo = row_m[r];
                float mn = fmaxf(mo, fmaxf(wmax[r], wmax[128 + r]));
                float cr = fexp2(mo - mn);
                mnew[mt][half] = mn; corr[mt][half] = cr;
                float ps = 0.0f;
#pragma unroll
                for (int nt = 0; nt < 4; nt++) {
                    float p0 = fexp2(acc_s[mt][nt][half * 2 + 0] - mn);
                    float p1 = fexp2(acc_s[mt][nt][half * 2 + 1] - mn);
                    ps += p0 + p1;
                    int c = wn * 32 + nt * 8 + 2 * tg;
                    Psu[r * AS + c]     = f2tf(p0);
                    Psu[r * AS + c + 1] = f2tf(p1);
                }
                ps += __shfl_xor_sync(0xffffffffu, ps, 1);
                ps += __shfl_xor_sync(0xffffffffu, ps, 2);
                if (tg == 0) wsum[wn * 128 + r] = ps;
                // rescale O
#pragma unroll
                for (int nt = 0; nt < 4; nt++) {
                    acc_o[mt][nt][half * 2 + 0] *= cr;
                    acc_o[mt][nt][half * 2 + 1] *= cr;
                }
            }
        asm volatile("cp.async.wait_group 1;" ::: "memory");   // V(t) done (K(t+1) pends)
        __syncthreads();                                        // [B] Psu/wsum complete, V visible

        // designated lanes update running stats (overlaps PV mma on other lanes)
        if (wn == 0 && tg == 0) {
#pragma unroll
            for (int mt = 0; mt < 2; mt++)
#pragma unroll
                for (int half = 0; half < 2; half++) {
                    int r = wm * 32 + mt * 16 + half * 8 + g;
                    row_l[r] = row_l[r] * corr[mt][half] + wsum[r] + wsum[128 + r];
                    row_m[r] = mnew[mt][half];
                }
        }

        // ---- O += P V ----
#pragma unroll
        for (int k8 = 0; k8 < 8; k8++) {
            unsigned a[2][4], b[4][2];
#pragma unroll
            for (int mt = 0; mt < 2; mt++) {
                int r = wm * 32 + mt * 16;
                a[mt][0] = Psu[(r + g) * AS + k8 * 8 + tg];
                a[mt][1] = Psu[(r + 8 + g) * AS + k8 * 8 + tg];
                a[mt][2] = Psu[(r + g) * AS + k8 * 8 + tg + 4];
                a[mt][3] = Psu[(r + 8 + g) * AS + k8 * 8 + tg + 4];
            }
#pragma unroll
            for (int nt = 0; nt < 4; nt++) {
                int c = wn * 32 + nt * 8 + g;          // output col (d)
                b[nt][0] = Vs[(k8 * 8 + tg) * AS + c];
                b[nt][1] = Vs[(k8 * 8 + tg + 4) * AS + c];
            }
#pragma unroll
            for (int mt = 0; mt < 2; mt++)
#pragma unroll
                for (int nt = 0; nt < 4; nt++)
                    mma_tf32(acc_o[mt][nt], a[mt], b[nt]);
        }
        __syncthreads();                            // [C] Vs reads done

        // issue V(t+1) (overlaps next tile's S-mma)
#pragma unroll
        for (int i = 0; i < 4; i++) {
            int r = ld_r + i * 16;
            cp_async16(vs_sm + (r * AS + ld_c) * 4, &vb[(size_t)(ktn + r) * DH + ld_c]);
        }
        asm volatile("cp.async.commit_group;" ::: "memory");
    }
    asm volatile("cp.async.wait_group 0;" ::: "memory");
    __syncthreads();

    // epilogue: normalize by row_l, write out
#pragma unroll
    for (int mt = 0; mt < 2; mt++)
#pragma unroll
        for (int half = 0; half < 2; half++) {
            int r = wm * 32 + mt * 16 + half * 8 + g;
            float inv = 1.0f / row_l[r];
#pragma unroll
            for (int nt = 0; nt < 4; nt++) {
                int c = wn * 32 + nt * 8 + 2 * tg;
                float* dst = &g_attn[(size_t)(q0 + r) * DM + h * DH + c];
                dst[0] = acc_o[mt][nt][half * 2 + 0] * inv;
                dst[1] = acc_o[mt][nt][half * 2 + 1] * inv;
            }
        }
}

// ---------------- launch ----------------
extern "C" void kernel_launch(void* const* d_in, const int* in_sizes, int n_in,
                              void* d_out, int out_size) {
    const float* obs   = (const float*)d_in[0];
    const float* cond  = (const float*)d_in[1];
    const float* vec   = (const float*)d_in[2];
    const float* pe    = (const float*)d_in[3];
    const float* o_mod_w = (const float*)d_in[4];
    const float* o_mod_b = (const float*)d_in[5];
    const float* o_qkv_w = (const float*)d_in[6];
    const float* o_q_s   = (const float*)d_in[7];
    const float* o_k_s   = (const float*)d_in[8];
    const float* o_proj_w = (const float*)d_in[9];
    const float* o_proj_b = (const float*)d_in[10];
    const float* o_mlp_w1 = (const float*)d_in[11];
    const float* o_mlp_b1 = (const float*)d_in[12];
    const float* o_mlp_w2 = (const float*)d_in[13];
    const float* o_mlp_b2 = (const float*)d_in[14];
    const float* c_mod_w = (const float*)d_in[15];
    const float* c_mod_b = (const float*)d_in[16];
    const float* c_qkv_w = (const float*)d_in[17];
    const float* c_q_s   = (const float*)d_in[18];
    const float* c_k_s   = (const float*)d_in[19];
    const float* c_proj_w = (const float*)d_in[20];
    const float* c_proj_b = (const float*)d_in[21];
    const float* c_mlp_w1 = (const float*)d_in[22];
    const float* c_mlp_b1 = (const float*)d_in[23];
    const float* c_mlp_w2 = (const float*)d_in[24];
    const float* c_mlp_b2 = (const float*)d_in[25];

    float* out = (float*)d_out;
    float* out_obs = out;                 // rows 0..LO-1
    float* out_cond = out + (size_t)LO * DM;

    float *p_xm, *p_qkv, *p_attn, *p_h;
    cudaGetSymbolAddress((void**)&p_xm, g_xm);
    cudaGetSymbolAddress((void**)&p_qkv, g_qkv);
    cudaGetSymbolAddress((void**)&p_attn, g_attn);
    cudaGetSymbolAddress((void**)&p_h, g_h);

    int smem_bytes = (int)((384 * AS) * 4 + (128 + 128 + 256 + 256) * 4);
    static int init = 0;
    if (!init) {
        init = 1;
        cudaFuncSetAttribute(attn_mma_kernel, cudaFuncAttributeMaxDynamicSharedMemorySize, smem_bytes);
    }

    // 1. modulation vectors (K-split for parallelism)
    mod_kernel<<<192, 256>>>(vec, o_mod_w, o_mod_b, c_mod_w, c_mod_b);

    // 2. LN + mod (chunks: 0=shift1, 1=scale1), merged
    ln_mod_kernel<<<LT, 256>>>(obs, cond, p_xm, 0, 1);

    // 3. qkv GEMMs, merged
    {
        dim3 g(3 * DM / 128, LT / 128);
        mma_gemm2_kernel<<<g, 256>>>(p_xm, o_qkv_w, p_qkv,
                                     p_xm + (size_t)LO * DM, c_qkv_w, p_qkv + (size_t)LO * 3 * DM,
                                     LO, 3 * DM, DM,
                                     nullptr, nullptr, nullptr, nullptr, -1, -1, 0);
    }

    // 4. rmsnorm + rope + scatter (tf32 pre-converted, warp-per-head)
    {
        dim3 b(32, 8);
        qkv_post_kernel<<<LT, b>>>(pe, o_q_s, o_k_s, c_q_s, c_k_s);
    }

    // 5. attention (tensor-core flash, cp.async pipelined, in-register softmax)
    {
        dim3 g(NH, LT / 128);
        attn_mma_kernel<<<g, 256, smem_bytes>>>();
    }

    // 6. proj + gated residual (gate1 = chunk 2), merged
    {
        dim3 g(DM / 128, LT / 128);
        mma_gemm2_kernel<<<g, 256>>>(p_attn + (size_t)LC * DM, o_proj_w, out_obs,
                                     p_attn, c_proj_w, out_cond,
                                     LO, DM, DM,
                                     o_proj_b, c_proj_b, obs, cond, 0 * 6 + 2, 1 * 6 + 2, 1);
    }

    // 7. LN2 + mod (chunks: 3=shift2, 4=scale2), merged
    ln_mod_kernel<<<LT, 256>>>(out_obs, out_cond, p_xm, 3, 4);

    // 8. mlp1 + gelu, merged
    {
        dim3 g(MH / 128, LT / 128);
        mma_gemm2_kernel<<<g, 256>>>(p_xm, o_mlp_w1, p_h,
                                     p_xm + (size_t)LO * DM, c_mlp_w1, p_h + (size_t)LO * MH,
                                     LO, MH, DM,
                                     o_mlp_b1, c_mlp_b1, nullptr, nullptr, -1, -1, 2);
    }

    // 9. mlp2 + gated residual (gate2 = chunk 5), merged, in-place residual on d_out
    {
        dim3 g(DM / 128, LT / 128);
        mma_gemm2_kernel<<<g, 256>>>(p_h, o_mlp_w2, out_obs,
                                     p_h + (size_t)LO * MH, c_mlp_w2, out_cond,
                                     LO, DM, MH,
                                     o_mlp_b2, c_mlp_b2, out_obs, out_cond, 0 * 6 + 5, 1 * 6 + 5, 1);
    }
}